// round 10
// baseline (speedup 1.0000x reference)
#include <cuda_runtime.h>
#include <cuda_bf16.h>
#include <cuda_fp16.h>
#include <math.h>
#include <stdint.h>

#define EDIM 768
#define NS 16
#define KC 4
#define RD 48
#define PD 80        // R + 2N
#define ZPNP 1024    // fused z(768) + params(80) padded to 1024
#define NDEPTH 4
#define VOC 32000
#define NB 2
#define LL 1024
#define HD 3072
#define BL (NB*LL)

typedef __half fp16;

// ---------------- scratch (device globals) ----------------
__device__ __align__(16) float g_x[BL*EDIM];
__device__ __align__(16) float g_xn[BL*EDIM];
__device__ __align__(16) float g_zp[BL*ZPNP];
__device__ __align__(16) float g_dt[BL*EDIM];
__device__ __align__(16) float g_u[BL*EDIM];
__device__ __align__(16) float g_thid[NB*HD];
__device__ __align__(16) float g_temb[NB*EDIM];

// fp16 activation buffers
__device__ __align__(16) fp16 g_xnf[BL*EDIM];
__device__ __align__(16) fp16 g_yf[BL*EDIM];
__device__ __align__(16) fp16 g_hidf[BL*HD];

// fp16 hi/lo weight buffers (converted once per call)
__device__ __align__(16) fp16 g_wzp_h[NDEPTH*ZPNP*EDIM];
__device__ __align__(16) fp16 g_wzp_l[NDEPTH*ZPNP*EDIM];
__device__ __align__(16) fp16 g_wout_h[NDEPTH*EDIM*EDIM];
__device__ __align__(16) fp16 g_wout_l[NDEPTH*EDIM*EDIM];
__device__ __align__(16) fp16 g_wm1_h[NDEPTH*HD*EDIM];
__device__ __align__(16) fp16 g_wm1_l[NDEPTH*HD*EDIM];
__device__ __align__(16) fp16 g_wm2_h[NDEPTH*EDIM*HD];
__device__ __align__(16) fp16 g_wm2_l[NDEPTH*EDIM*HD];
__device__ __align__(16) fp16 g_whd_h[(size_t)VOC*EDIM];
__device__ __align__(16) fp16 g_whd_l[(size_t)VOC*EDIM];

// ---------------- helpers ----------------
__device__ __forceinline__ float siluf(float x) { return x / (1.0f + expf(-x)); }
__device__ __forceinline__ float geluf(float x) { return 0.5f * x * (1.0f + erff(x * 0.7071067811865476f)); }
__device__ __forceinline__ float softplusf(float x) { return (x > 20.0f) ? x : log1pf(expf(x)); }

__device__ __forceinline__ float warpsum(float v) {
    #pragma unroll
    for (int o = 16; o > 0; o >>= 1) v += __shfl_down_sync(0xffffffffu, v, o);
    return v;
}

__device__ __forceinline__ uint32_t smem_to_u32(const void* smem_ptr) {
    uint32_t addr;
    asm("{ .reg .u64 tmp; cvta.to.shared.u64 tmp, %1; cvt.u32.u64 %0, tmp; }"
        : "=r"(addr) : "l"(smem_ptr));
    return addr;
}

__device__ __forceinline__ void ldsm_x4(uint32_t& r0, uint32_t& r1, uint32_t& r2, uint32_t& r3,
                                        uint32_t addr) {
    asm volatile("ldmatrix.sync.aligned.m8n8.x4.shared.b16 {%0,%1,%2,%3}, [%4];"
                 : "=r"(r0), "=r"(r1), "=r"(r2), "=r"(r3) : "r"(addr));
}

__device__ __forceinline__ void mma16816h(float* c, const uint32_t* a, uint32_t b0, uint32_t b1) {
    asm volatile(
        "mma.sync.aligned.m16n8k16.row.col.f32.f16.f16.f32 "
        "{%0,%1,%2,%3}, {%4,%5,%6,%7}, {%8,%9}, {%0,%1,%2,%3};\n"
        : "+f"(c[0]), "+f"(c[1]), "+f"(c[2]), "+f"(c[3])
        : "r"(a[0]), "r"(a[1]), "r"(a[2]), "r"(a[3]), "r"(b0), "r"(b1));
}

#define CP_ASYNC16(dst, src) \
    asm volatile("cp.async.cg.shared.global [%0], [%1], 16;" :: "r"(dst), "l"(src) : "memory")
#define CP_COMMIT() asm volatile("cp.async.commit_group;" ::: "memory")
#define CP_WAIT(n)  asm volatile("cp.async.wait_group %0;" :: "n"(n) : "memory")

// ---------------- fused weight conversion + time_mlp1 (single launch) --------
#define NW1 ((size_t)NDEPTH*ZPNP*EDIM)
#define NW2 ((size_t)NDEPTH*EDIM*EDIM)
#define NW3 ((size_t)NDEPTH*HD*EDIM)
#define NW4 ((size_t)NDEPTH*EDIM*HD)
#define NW5 ((size_t)VOC*EDIM)
#define NWTOT (NW1+NW2+NW3+NW4+NW5)
#define NWB ((unsigned)((NWTOT + 255) / 256))
#define TM1B ((NB*HD)/8)

__global__ void cvt_tm1_kernel(
    const float* __restrict__ z_w, const float* __restrict__ p_w,
    const float* __restrict__ out_w, const float* __restrict__ mlp_w1,
    const float* __restrict__ mlp_w2, const float* __restrict__ head_w,
    fp16* __restrict__ wzph, fp16* __restrict__ wzpl,
    fp16* __restrict__ wouth, fp16* __restrict__ woutl,
    fp16* __restrict__ wm1h, fp16* __restrict__ wm1l,
    fp16* __restrict__ wm2h, fp16* __restrict__ wm2l,
    fp16* __restrict__ whdh, fp16* __restrict__ whdl,
    const int* __restrict__ timesteps,
    const float* __restrict__ time_w1, const float* __restrict__ time_b1,
    float* __restrict__ thid)
{
    if (blockIdx.x >= NWB) {
        int gw = (blockIdx.x - NWB) * 8 + (threadIdx.x >> 5);
        int ln = threadIdx.x & 31;
        if (gw >= NB * HD) return;
        int b = gw / HD, hh = gw % HD;
        const int half_ = EDIM / 2;
        float t = (float)timesteps[b];
        const float* w = time_w1 + (size_t)hh * EDIM;
        float s = 0.f;
        for (int k = ln; k < EDIM; k += 32) {
            int j = (k < half_) ? k : (k - half_);
            float freq = expf(-9.210340371976184f * (float)j / (float)half_);
            float arg = t * freq;
            float emb = (k < half_) ? sinf(arg) : cosf(arg);
            s += emb * w[k];
        }
        s = warpsum(s);
        if (ln == 0) { s += time_b1[hh]; thid[gw] = siluf(s); }
        return;
    }
    size_t i = (size_t)blockIdx.x * 256 + threadIdx.x;
    if (i >= NWTOT) return;
    float v; fp16 *ph, *pl; size_t j;
    if (i < NW1) {
        j = i;
        int c = j % EDIM;
        int r = (j / EDIM) % ZPNP;
        int d = j / ((size_t)ZPNP * EDIM);
        if (r < EDIM)           v = z_w[((size_t)d * EDIM + r) * EDIM + c];
        else if (r - EDIM < PD) v = p_w[((size_t)d * PD + (r - EDIM)) * EDIM + c];
        else                    v = 0.f;
        ph = wzph + j; pl = wzpl + j;
    } else if (i < NW1 + NW2) {
        j = i - NW1; v = out_w[j]; ph = wouth + j; pl = woutl + j;
    } else if (i < NW1 + NW2 + NW3) {
        j = i - NW1 - NW2; v = mlp_w1[j]; ph = wm1h + j; pl = wm1l + j;
    } else if (i < NW1 + NW2 + NW3 + NW4) {
        j = i - NW1 - NW2 - NW3; v = mlp_w2[j]; ph = wm2h + j; pl = wm2l + j;
    } else {
        j = i - NW1 - NW2 - NW3 - NW4; v = head_w[j]; ph = whdh + j; pl = whdl + j;
    }
    fp16 hv = __float2half_rn(v);
    *ph = hv;
    *pl = __float2half_rn(v - __half2float(hv));
}

__global__ void time_mlp2(const float* __restrict__ w2, const float* __restrict__ b2,
                          const float* __restrict__ thid, float* __restrict__ temb) {
    int gw = (blockIdx.x * blockDim.x + threadIdx.x) >> 5;
    int ln = threadIdx.x & 31;
    if (gw >= NB * EDIM) return;
    int b = gw / EDIM, e = gw % EDIM;
    const float* h = thid + b * HD;
    const float* w = w2 + (size_t)e * HD;
    float s = 0.f;
    for (int k = ln; k < HD; k += 32) s += h[k] * w[k];
    s = warpsum(s);
    if (ln == 0) temb[gw] = s + b2[e];
}

// ---------------- embed + layer-0 LN1 fused ----------------
__global__ void embed_ln1_kernel(const int* __restrict__ tokens,
                                 const float* __restrict__ tok_emb,
                                 const float* __restrict__ temb,
                                 const float* __restrict__ g, const float* __restrict__ bia,
                                 float* __restrict__ x, float* __restrict__ xn,
                                 fp16* __restrict__ of) {
    int row = blockIdx.x;
    int b = row / LL;
    int tok = tokens[row];
    const float* te = tok_emb + (size_t)tok * EDIM;
    const float* tb = temb + b * EDIM;
    __shared__ float sv[EDIM];
    float s = 0.f, s2 = 0.f;
    for (int e = threadIdx.x; e < EDIM; e += blockDim.x) {
        float v = te[e] + tb[e];
        sv[e] = v;
        x[(size_t)row * EDIM + e] = v;
        s += v; s2 += v * v;
    }
    __shared__ float sh1[8], sh2[8];
    __shared__ float smu, srs;
    int w = threadIdx.x >> 5, ln = threadIdx.x & 31;
    s = warpsum(s); s2 = warpsum(s2);
    if (ln == 0) { sh1[w] = s; sh2[w] = s2; }
    __syncthreads();
    if (threadIdx.x == 0) {
        float a = 0.f, c = 0.f;
        #pragma unroll
        for (int i = 0; i < 8; i++) { a += sh1[i]; c += sh2[i]; }
        float mu = a / EDIM;
        float var = c / EDIM - mu * mu;
        smu = mu; srs = rsqrtf(var + 1e-5f);
    }
    __syncthreads();
    float mu = smu, rs = srs;
    float* o = xn + (size_t)row * EDIM;
    fp16* pf = of + (size_t)row * EDIM;
    for (int e = threadIdx.x; e < EDIM; e += blockDim.x) {
        float v = (sv[e] - mu) * rs * g[e] + bia[e];
        o[e] = v;
        pf[e] = __float2half_rn(v);
    }
}

// ---------------- layernorm: fp32 out + fp16 out ----------------
__global__ void ln_kernel(const float* __restrict__ in, float* __restrict__ out,
                          fp16* __restrict__ of,
                          const float* __restrict__ g, const float* __restrict__ bia) {
    int row = blockIdx.x;
    const float* x = in + (size_t)row * EDIM;
    float s = 0.f, s2 = 0.f;
    for (int e = threadIdx.x; e < EDIM; e += blockDim.x) { float v = x[e]; s += v; s2 += v * v; }
    __shared__ float sh1[8], sh2[8];
    __shared__ float smu, srs;
    int w = threadIdx.x >> 5, ln = threadIdx.x & 31;
    s = warpsum(s); s2 = warpsum(s2);
    if (ln == 0) { sh1[w] = s; sh2[w] = s2; }
    __syncthreads();
    if (threadIdx.x == 0) {
        float a = 0.f, c = 0.f;
        #pragma unroll
        for (int i = 0; i < 8; i++) { a += sh1[i]; c += sh2[i]; }
        float mu = a / EDIM;
        float var = c / EDIM - mu * mu;
        smu = mu; srs = rsqrtf(var + 1e-5f);
    }
    __syncthreads();
    float mu = smu, rs = srs;
    float* o = out + (size_t)row * EDIM;
    fp16* pf = of + (size_t)row * EDIM;
    for (int e = threadIdx.x; e < EDIM; e += blockDim.x) {
        float v = (x[e] - mu) * rs * g[e] + bia[e];
        o[e] = v;
        pf[e] = __float2half_rn(v);
    }
}

// ---------------- depthwise causal conv + silu ----------------
__global__ void conv_silu(const float* __restrict__ xn, const float* __restrict__ w,
                          float* __restrict__ u) {
    int idx = blockIdx.x * blockDim.x + threadIdx.x;
    if (idx >= BL * EDIM) return;
    int e = idx % EDIM, bl = idx / EDIM, l = bl % LL, b = bl / LL;
    const float* base = xn + (size_t)b * LL * EDIM + e;
    float acc = 0.f;
    #pragma unroll
    for (int k = 0; k < KC; k++) {
        int ls = l - (KC - 1) + k;
        if (ls >= 0) acc += base[(size_t)ls * EDIM] * w[e * KC + k];
    }
    u[idx] = siluf(acc);
}

// ---------------- SSM scan with prefetch; outputs fp16 ----------------
__global__ void scan_kernel(const float* __restrict__ Alog, const float* __restrict__ Dp,
                            const float* __restrict__ dt, const float* __restrict__ u,
                            const float* __restrict__ zp,
                            fp16* __restrict__ yf) {
    int g = blockIdx.x * blockDim.x + threadIdx.x;
    if (g >= NB * EDIM * NS) return;
    int n = g & (NS - 1);
    int pe = g >> 4;
    int e = pe % EDIM, b = pe / EDIM;

    float av = -expf(Alog[(size_t)e * NS + n]);
    float invA = 1.0f / (av + 1e-10f);
    bool smallA = fabsf(av) < 1e-5f;
    float D = Dp[e];

    const float* dtp = dt + (size_t)b * LL * EDIM + e;
    const float* up  = u  + (size_t)b * LL * EDIM + e;
    const float* zb  = zp + (size_t)b * LL * ZPNP;
    const float* cpp = zb + EDIM + RD + NS + n;
    const float* zgp = zb + e;
    fp16* yp = yf + (size_t)b * LL * EDIM + e;

    float dtl = dtp[0];
    float ul  = up[0];
    float cv  = cpp[0];
    float zv  = (n == 0) ? zgp[0] : 0.f;

    float h = 0.f, dd = 0.f, uu = 0.f;
    for (int l = 0; l < LL; l++) {
        float dtc = dtl, uc = ul, cc = cv, zc = zv;
        if (l + 1 < LL) {
            dtl = dtp[(size_t)(l + 1) * EDIM];
            ul  = up[(size_t)(l + 1) * EDIM];
            cv  = cpp[(size_t)(l + 1) * ZPNP];
            if (n == 0) zv = zgp[(size_t)(l + 1) * ZPNP];
        }
        float de = (l == 0) ? dtc : dd;
        float ue = (l == 0) ? uc  : uu;
        float At = __expf(de * av);
        float Bt = smallA ? de : (At - 1.0f) * invA;
        h = fmaf(At, h, Bt * ue);
        float yy = cc * h;
        yy += __shfl_xor_sync(0xffffffffu, yy, 1);
        yy += __shfl_xor_sync(0xffffffffu, yy, 2);
        yy += __shfl_xor_sync(0xffffffffu, yy, 4);
        yy += __shfl_xor_sync(0xffffffffu, yy, 8);
        if (n == 0) {
            float v = (yy + uc * D) * siluf(zc);
            yp[(size_t)l * EDIM] = __float2half_rn(v);
        }
        dd = dtc; uu = uc;
    }
}

// ---------------- SIMT GEMM (dt projection: K=48) -------
template<int ACT, bool BIAS, bool ACC>
__global__ void __launch_bounds__(256) gemm_tn(
    const float* __restrict__ A, int lda,
    const float* __restrict__ Bm, int ldb,
    const float* __restrict__ bias,
    float* __restrict__ C, int ldc,
    int M, int N, int K)
{
    __shared__ float As[8][132];
    __shared__ float Bs[8][132];
    int tid = threadIdx.x;
    int bm = blockIdx.y, bn = blockIdx.x;
    int tx = tid % 16, ty = tid / 16;

    float acc[8][8];
    #pragma unroll
    for (int i = 0; i < 8; i++)
        #pragma unroll
        for (int j = 0; j < 8; j++) acc[i][j] = 0.f;

    int ar = tid >> 1;
    int ak = (tid & 1) * 4;
    const float* Ab = A + (size_t)(bm * 128 + ar) * lda + ak;
    int brow = bn * 128 + ar;
    const float* Bb = Bm + (size_t)brow * ldb + ak;
    bool bvalid = brow < N;

    for (int k0 = 0; k0 < K; k0 += 8) {
        float4 av = *(const float4*)(Ab + k0);
        float4 bv = bvalid ? *(const float4*)(Bb + k0) : make_float4(0.f,0.f,0.f,0.f);
        As[ak+0][ar] = av.x; As[ak+1][ar] = av.y; As[ak+2][ar] = av.z; As[ak+3][ar] = av.w;
        Bs[ak+0][ar] = bv.x; Bs[ak+1][ar] = bv.y; Bs[ak+2][ar] = bv.z; Bs[ak+3][ar] = bv.w;
        __syncthreads();
        #pragma unroll
        for (int kk = 0; kk < 8; kk++) {
            float4 a0 = *(const float4*)(&As[kk][ty*8]);
            float4 a1 = *(const float4*)(&As[kk][ty*8+4]);
            float4 b0 = *(const float4*)(&Bs[kk][tx*8]);
            float4 b1 = *(const float4*)(&Bs[kk][tx*8+4]);
            float arf[8] = {a0.x,a0.y,a0.z,a0.w,a1.x,a1.y,a1.z,a1.w};
            float brf[8] = {b0.x,b0.y,b0.z,b0.w,b1.x,b1.y,b1.z,b1.w};
            #pragma unroll
            for (int i = 0; i < 8; i++)
                #pragma unroll
                for (int j = 0; j < 8; j++)
                    acc[i][j] = fmaf(arf[i], brf[j], acc[i][j]);
        }
        __syncthreads();
    }

    int row0 = bm * 128 + ty * 8;
    int col0 = bn * 128 + tx * 8;
    #pragma unroll
    for (int i = 0; i < 8; i++) {
        float* Crow = C + (size_t)(row0 + i) * ldc;
        #pragma unroll
        for (int jv = 0; jv < 8; jv += 4) {
            int col = col0 + jv;
            if (col < N) {
                float4 v = make_float4(acc[i][jv], acc[i][jv+1], acc[i][jv+2], acc[i][jv+3]);
                if (BIAS) {
                    v.x += bias[col]; v.y += bias[col+1]; v.z += bias[col+2]; v.w += bias[col+3];
                }
                if (ACT == 1) { v.x = softplusf(v.x); v.y = softplusf(v.y); v.z = softplusf(v.z); v.w = softplusf(v.w); }
                if (ACT == 2) { v.x = geluf(v.x); v.y = geluf(v.y); v.z = geluf(v.z); v.w = geluf(v.w); }
                if (ACC) {
                    float4 old = *(const float4*)(&Crow[col]);
                    v.x += old.x; v.y += old.y; v.z += old.z; v.w += old.w;
                }
                *(float4*)(&Crow[col]) = v;
            }
        }
    }
}

// ================= fp16 2-term mma GEMM: 64x64 tile, 4 warps, 3-stage ========
// Used for out-proj / mlp2 (small N -> needs small tiles to fill the chip).
#define GSTAGE 12288
#define GSMEM  (3*GSTAGE)

__device__ __forceinline__ void g_load_stage(
    uint32_t st, const fp16* __restrict__ A,
    const fp16* __restrict__ Bh, const fp16* __restrict__ Bl,
    int K, int koff, int tid)
{
    int r = tid >> 1;                // 0..63
    int gb = (tid & 1) * 2;
    size_t ro = (size_t)r * K + koff;
    #pragma unroll
    for (int gi = 0; gi < 2; gi++) {
        int g = gb + gi;
        uint32_t so = (uint32_t)(r * 64 + ((g ^ ((r >> 1) & 3)) << 4));
        CP_ASYNC16(st + so,          A  + ro + g * 8);
        CP_ASYNC16(st + 4096 + so,   Bh + ro + g * 8);
        CP_ASYNC16(st + 8192 + so,   Bl + ro + g * 8);
    }
}

template<int ACT, bool BIAS, int OUT>
__global__ void __launch_bounds__(128, 6) gemm_f16(
    const fp16* __restrict__ A,
    const fp16* __restrict__ Bh, const fp16* __restrict__ Bl,
    int K, const float* __restrict__ bias,
    float* __restrict__ C, fp16* __restrict__ Cf,
    int ldc, int nmax)
{
    extern __shared__ __align__(16) unsigned char smem_raw[];
    uint32_t sb = smem_to_u32(smem_raw);

    int tid = threadIdx.x;
    int wid = tid >> 5, lid = tid & 31;
    int wm = wid & 1, wn = wid >> 1;     // 2(m) x 2(n)

    const fp16* A0  = A  + (size_t)(blockIdx.x * 64) * K;
    const fp16* Bh0 = Bh + (size_t)(blockIdx.y * 64) * K;
    const fp16* Bl0 = Bl + (size_t)(blockIdx.y * 64) * K;

    float acc[2][4][4];
    #pragma unroll
    for (int i = 0; i < 2; i++)
        #pragma unroll
        for (int j = 0; j < 4; j++)
            #pragma unroll
            for (int q = 0; q < 4; q++) acc[i][j][q] = 0.f;

    int NC = K / 32;
    g_load_stage(sb, A0, Bh0, Bl0, K, 0, tid);
    CP_COMMIT();
    g_load_stage(sb + GSTAGE, A0, Bh0, Bl0, K, 32, tid);
    CP_COMMIT();

    for (int c = 0; c < NC; c++) {
        if (c + 1 < NC) { CP_WAIT(1); } else { CP_WAIT(0); }
        __syncthreads();
        if (c + 2 < NC) {
            g_load_stage(sb + ((c + 2) % 3) * GSTAGE, A0, Bh0, Bl0, K, (c + 2) * 32, tid);
            CP_COMMIT();
        }

        uint32_t st = sb + (c % 3) * GSTAGE;
        uint32_t sA = st, sBh = st + 4096, sBl = st + 8192;

        #pragma unroll
        for (int ks = 0; ks < 2; ks++) {
            int kch = 2 * ks + (lid >> 4);
            uint32_t bh[2][4], bl_[2][4];
            #pragma unroll
            for (int j2 = 0; j2 < 2; j2++) {
                int mrow = wn * 32 + j2 * 16 + ((lid >> 3) & 1) * 8 + (lid & 7);
                uint32_t off = (uint32_t)(mrow * 64)
                             + (((uint32_t)kch ^ (((uint32_t)mrow >> 1) & 3u)) << 4);
                ldsm_x4(bh[j2][0], bh[j2][1], bh[j2][2], bh[j2][3], sBh + off);
                ldsm_x4(bl_[j2][0], bl_[j2][1], bl_[j2][2], bl_[j2][3], sBl + off);
            }
            #pragma unroll
            for (int i = 0; i < 2; i++) {
                int arow = wm * 32 + i * 16 + (lid & 15);
                uint32_t off = (uint32_t)(arow * 64)
                             + (((uint32_t)kch ^ (((uint32_t)arow >> 1) & 3u)) << 4);
                uint32_t ah[4];
                ldsm_x4(ah[0], ah[1], ah[2], ah[3], sA + off);
                #pragma unroll
                for (int j = 0; j < 4; j++) {
                    int j2 = j >> 1, js = j & 1;
                    mma16816h(acc[i][j], ah, bh[j2][js], bh[j2][2 + js]);
                    mma16816h(acc[i][j], ah, bl_[j2][js], bl_[j2][2 + js]);
                }
            }
        }
    }

    int lr = lid >> 2;
    int lc = (lid & 3) * 2;
    #pragma unroll
    for (int i = 0; i < 2; i++) {
        int row = blockIdx.x * 64 + wm * 32 + i * 16 + lr;
        #pragma unroll
        for (int j = 0; j < 4; j++) {
            int col0 = blockIdx.y * 64 + wn * 32 + j * 8 + lc;
            if (col0 < nmax) {
                #pragma unroll
                for (int half = 0; half < 2; half++) {
                    int rr = row + half * 8;
                    float v0 = acc[i][j][half * 2 + 0];
                    float v1 = acc[i][j][half * 2 + 1];
                    if (BIAS) { v0 += bias[col0]; v1 += bias[col0 + 1]; }
                    if (ACT == 1) { v0 = softplusf(v0); v1 = softplusf(v1); }
                    if (ACT == 2) { v0 = geluf(v0); v1 = geluf(v1); }
                    if (OUT == 2) {
                        __half2* pf = (__half2*)(Cf + (size_t)rr * ldc + col0);
                        *pf = __floats2half2_rn(v0, v1);
                    } else {
                        float* cp = C + (size_t)rr * ldc + col0;
                        if (OUT == 1) {
                            float2 old = *(const float2*)cp;
                            v0 += old.x; v1 += old.y;
                        }
                        *(float2*)cp = make_float2(v0, v1);
                    }
                }
            }
        }
    }
}

// ========== fp16 2-term mma GEMM: CTA 128x128, 4 warps, warp tile 128x32 =====
// Tall warp tile: 12 ldsm.x4 per 64 MMAs -> ~10.7 useful FLOP per smem byte.
// Used for zp, mlp1, head (grids that fill the chip at 128x128 tiles).
#define WSTAGE 24576
#define WSMEM  (3*WSTAGE)

__device__ __forceinline__ void w_load_stage(
    uint32_t st, const fp16* __restrict__ A,
    const fp16* __restrict__ Bh, const fp16* __restrict__ Bl,
    int K, int koff, int tid)
{
    int r = tid;                      // 0..127
    size_t ro = (size_t)r * K + koff;
    #pragma unroll
    for (int g = 0; g < 4; g++) {
        uint32_t so = (uint32_t)(r * 64 + ((g ^ ((r >> 1) & 3)) << 4));
        CP_ASYNC16(st + so,           A  + ro + g * 8);
        CP_ASYNC16(st + 8192 + so,    Bh + ro + g * 8);
        CP_ASYNC16(st + 16384 + so,   Bl + ro + g * 8);
    }
}

template<int ACT, bool BIAS, int OUT>
__global__ void __launch_bounds__(128, 2) gemm_w128(
    const fp16* __restrict__ A,
    const fp16* __restrict__ Bh, const fp16* __restrict__ Bl,
    int K, const float* __restrict__ bias,
    float* __restrict__ C, fp16* __restrict__ Cf,
    int ldc, int nmax)
{
    extern __shared__ __align__(16) unsigned char smem_raw[];
    uint32_t sb = smem_to_u32(smem_raw);

    int tid = threadIdx.x;
    int wn = tid >> 5, lid = tid & 31;   // 4 warps, each: all 128 m x 32 n

    const fp16* A0  = A  + (size_t)(blockIdx.x * 128) * K;
    const fp16* Bh0 = Bh + (size_t)(blockIdx.y * 128) * K;
    const fp16* Bl0 = Bl + (size_t)(blockIdx.y * 128) * K;

    float acc[8][4][4];
    #pragma unroll
    for (int i = 0; i < 8; i++)
        #pragma unroll
        for (int j = 0; j < 4; j++)
            #pragma unroll
            for (int q = 0; q < 4; q++) acc[i][j][q] = 0.f;

    int NC = K / 32;
    w_load_stage(sb, A0, Bh0, Bl0, K, 0, tid);
    CP_COMMIT();
    w_load_stage(sb + WSTAGE, A0, Bh0, Bl0, K, 32, tid);
    CP_COMMIT();

    for (int c = 0; c < NC; c++) {
        if (c + 1 < NC) { CP_WAIT(1); } else { CP_WAIT(0); }
        __syncthreads();
        if (c + 2 < NC) {
            w_load_stage(sb + ((c + 2) % 3) * WSTAGE, A0, Bh0, Bl0, K, (c + 2) * 32, tid);
            CP_COMMIT();
        }

        uint32_t st = sb + (c % 3) * WSTAGE;
        uint32_t sA = st, sBh = st + 8192, sBl = st + 16384;

        #pragma unroll
        for (int ks = 0; ks < 2; ks++) {
            int kch = 2 * ks + (lid >> 4);
            uint32_t bh[2][4], bl_[2][4];
            #pragma unroll
            for (int j2 = 0; j2 < 2; j2++) {
                int mrow = wn * 32 + j2 * 16 + ((lid >> 3) & 1) * 8 + (lid & 7);
                uint32_t off = (uint32_t)(mrow * 64)
                             + (((uint32_t)kch ^ (((uint32_t)mrow >> 1) & 3u)) << 4);
                ldsm_x4(bh[j2][0], bh[j2][1], bh[j2][2], bh[j2][3], sBh + off);
                ldsm_x4(bl_[j2][0], bl_[j2][1], bl_[j2][2], bl_[j2][3], sBl + off);
            }
            #pragma unroll
            for (int i = 0; i < 8; i++) {
                int arow = i * 16 + (lid & 15);
                uint32_t off = (uint32_t)(arow * 64)
                             + (((uint32_t)kch ^ (((uint32_t)arow >> 1) & 3u)) << 4);
                uint32_t ah[4];
                ldsm_x4(ah[0], ah[1], ah[2], ah[3], sA + off);
                #pragma unroll
                for (int j = 0; j < 4; j++) {
                    int j2 = j >> 1, js = j & 1;
                    mma16816h(acc[i][j], ah, bh[j2][js], bh[j2][2 + js]);
                    mma16816h(acc[i][j], ah, bl_[j2][js], bl_[j2][2 + js]);
                }
            }
        }
    }

    int lr = lid >> 2;
    int lc = (lid & 3) * 2;
    #pragma unroll
    for (int i = 0; i < 8; i++) {
        int row = blockIdx.x * 128 + i * 16 + lr;
        #pragma unroll
        for (int j = 0; j < 4; j++) {
            int col0 = blockIdx.y * 128 + wn * 32 + j * 8 + lc;
            if (col0 < nmax) {
                #pragma unroll
                for (int half = 0; half < 2; half++) {
                    int rr = row + half * 8;
                    float v0 = acc[i][j][half * 2 + 0];
                    float v1 = acc[i][j][half * 2 + 1];
                    if (BIAS) { v0 += bias[col0]; v1 += bias[col0 + 1]; }
                    if (ACT == 1) { v0 = softplusf(v0); v1 = softplusf(v1); }
                    if (ACT == 2) { v0 = geluf(v0); v1 = geluf(v1); }
                    if (OUT == 2) {
                        __half2* pf = (__half2*)(Cf + (size_t)rr * ldc + col0);
                        *pf = __floats2half2_rn(v0, v1);
                    } else {
                        float* cp = C + (size_t)rr * ldc + col0;
                        if (OUT == 1) {
                            float2 old = *(const float2*)cp;
                            v0 += old.x; v1 += old.y;
                        }
                        *(float2*)cp = make_float2(v0, v1);
                    }
                }
            }
        }
    }
}

// ---------------- launch ----------------
extern "C" void kernel_launch(void* const* d_in, const int* in_sizes, int n_in,
                              void* d_out, int out_size) {
    const int*   tokens    = (const int*)  d_in[0];
    const int*   timesteps = (const int*)  d_in[1];
    const float* tok_emb   = (const float*)d_in[2];
    const float* time_w1   = (const float*)d_in[3];
    const float* time_b1   = (const float*)d_in[4];
    const float* time_w2   = (const float*)d_in[5];
    const float* time_b2   = (const float*)d_in[6];
    const float* ln1_g     = (const float*)d_in[7];
    const float* ln1_b     = (const float*)d_in[8];
    const float* z_w       = (const float*)d_in[9];
    const float* p_w       = (const float*)d_in[10];
    const float* conv_w    = (const float*)d_in[11];
    const float* dtp_w     = (const float*)d_in[12];
    const float* dtp_b     = (const float*)d_in[13];
    const float* A_log     = (const float*)d_in[14];
    const float* D_param   = (const float*)d_in[15];
    const float* out_w     = (const float*)d_in[16];
    const float* ln2_g     = (const float*)d_in[17];
    const float* ln2_b     = (const float*)d_in[18];
    const float* mlp_w1    = (const float*)d_in[19];
    const float* mlp_b1    = (const float*)d_in[20];
    const float* mlp_w2    = (const float*)d_in[21];
    const float* mlp_b2    = (const float*)d_in[22];
    const float* lnout_g   = (const float*)d_in[23];
    const float* lnout_b   = (const float*)d_in[24];
    const float* head_w    = (const float*)d_in[25];
    const float* head_b    = (const float*)d_in[26];

    #define GETP(sym, var, type) void* _p_##var; cudaGetSymbolAddress(&_p_##var, sym); type* var = (type*)_p_##var
    GETP(g_x, bx, float);       GETP(g_xn, bxn, float);
    GETP(g_zp, bzp, float);     GETP(g_dt, bdt, float);
    GETP(g_u, bu, float);
    GETP(g_thid, bthid, float); GETP(g_temb, btemb, float);
    GETP(g_xnf, bxnf, fp16);    GETP(g_yf, byf, fp16);     GETP(g_hidf, bhidf, fp16);
    GETP(g_wzp_h, wzph, fp16);  GETP(g_wzp_l, wzpl, fp16);
    GETP(g_wout_h, wouth, fp16);GETP(g_wout_l, woutl, fp16);
    GETP(g_wm1_h, wm1h, fp16);  GETP(g_wm1_l, wm1l, fp16);
    GETP(g_wm2_h, wm2h, fp16);  GETP(g_wm2_l, wm2l, fp16);
    GETP(g_whd_h, whdh, fp16);  GETP(g_whd_l, whdl, fp16);
    #undef GETP

    cudaFuncSetAttribute(gemm_f16<0,false,1>, cudaFuncAttributeMaxDynamicSharedMemorySize, GSMEM);
    cudaFuncSetAttribute(gemm_f16<0,true, 1>, cudaFuncAttributeMaxDynamicSharedMemorySize, GSMEM);
    cudaFuncSetAttribute(gemm_w128<0,false,0>, cudaFuncAttributeMaxDynamicSharedMemorySize, WSMEM);
    cudaFuncSetAttribute(gemm_w128<2,true, 2>, cudaFuncAttributeMaxDynamicSharedMemorySize, WSMEM);
    cudaFuncSetAttribute(gemm_w128<0,true, 0>, cudaFuncAttributeMaxDynamicSharedMemorySize, WSMEM);

    // 1: fused weight conversion + time_mlp1
    cvt_tm1_kernel<<<NWB + TM1B, 256>>>(
        z_w, p_w, out_w, mlp_w1, mlp_w2, head_w,
        wzph, wzpl, wouth, woutl, wm1h, wm1l, wm2h, wm2l, whdh, whdl,
        timesteps, time_w1, time_b1, bthid);
    // 2: time_mlp2
    time_mlp2<<<(NB*EDIM*32 + 255)/256, 256>>>(time_w2, time_b2, bthid, btemb);
    // 3: embed + layer-0 LN1
    embed_ln1_kernel<<<BL, 256>>>(tokens, tok_emb, btemb, ln1_g, ln1_b,
                                  bx, bxn, bxnf);

    for (int i = 0; i < NDEPTH; i++) {
        const fp16* wzph_i = wzph + (size_t)i * ZPNP * EDIM;
        const fp16* wzpl_i = wzpl + (size_t)i * ZPNP * EDIM;
        const fp16* wouth_i = wouth + (size_t)i * EDIM * EDIM;
        const fp16* woutl_i = woutl + (size_t)i * EDIM * EDIM;
        const fp16* wm1h_i = wm1h + (size_t)i * HD * EDIM;
        const fp16* wm1l_i = wm1l + (size_t)i * HD * EDIM;
        const fp16* wm2h_i = wm2h + (size_t)i * EDIM * HD;
        const fp16* wm2l_i = wm2l + (size_t)i * EDIM * HD;
        const float* cwi  = conv_w + (size_t)i * EDIM * KC;
        const float* dtwi = dtp_w + (size_t)i * EDIM * RD;
        const float* dtbi = dtp_b + (size_t)i * EDIM;
        const float* ali  = A_log + (size_t)i * EDIM * NS;
        const float* dpi  = D_param + (size_t)i * EDIM;
        const float* b1i  = mlp_b1 + (size_t)i * HD;
        const float* b2i  = mlp_b2 + (size_t)i * EDIM;

        if (i > 0)
            ln_kernel<<<BL, 256>>>(bx, bxn, bxnf, ln1_g + i*EDIM, ln1_b + i*EDIM);
        // 4 (first iter): zp GEMM — in ncu capture window (tall-tile kernel)
        gemm_w128<0,false,0><<<dim3(BL/128, ZPNP/128), 128, WSMEM>>>(
            bxnf, wzph_i, wzpl_i, EDIM, nullptr, bzp, nullptr, ZPNP, ZPNP);
        gemm_tn<1,true,false><<<dim3(EDIM/128, BL/128), 256>>>(
            bzp + EDIM, ZPNP, dtwi, RD, dtbi, bdt, EDIM, BL, EDIM, RD);
        conv_silu<<<(BL*EDIM + 255)/256, 256>>>(bxn, cwi, bu);
        scan_kernel<<<(NB*EDIM*NS + 255)/256, 256>>>(ali, dpi, bdt, bu, bzp, byf);
        gemm_f16<0,false,1><<<dim3(BL/64, EDIM/64), 128, GSMEM>>>(
            byf, wouth_i, woutl_i, EDIM, nullptr, bx, nullptr, EDIM, EDIM);
        ln_kernel<<<BL, 256>>>(bx, bxn, bxnf, ln2_g + i*EDIM, ln2_b + i*EDIM);
        gemm_w128<2,true,2><<<dim3(BL/128, HD/128), 128, WSMEM>>>(
            bxnf, wm1h_i, wm1l_i, EDIM, b1i, nullptr, bhidf, HD, HD);
        gemm_f16<0,true,1><<<dim3(BL/64, EDIM/64), 128, GSMEM>>>(
            bhidf, wm2h_i, wm2l_i, HD, b2i, bx, nullptr, EDIM, EDIM);
    }

    ln_kernel<<<BL, 256>>>(bx, bxn, bxnf, lnout_g, lnout_b);
    gemm_w128<0,true,0><<<dim3(BL/128, VOC/128), 128, WSMEM>>>(
        bxnf, whdh, whdl, EDIM, head_b, (float*)d_out, nullptr, VOC, VOC);
}

// round 11
// speedup vs baseline: 1.1729x; 1.1729x over previous
#include <cuda_runtime.h>
#include <cuda_bf16.h>
#include <cuda_fp16.h>
#include <math.h>
#include <stdint.h>

#define EDIM 768
#define NS 16
#define KC 4
#define RD 48
#define PD 80        // R + 2N
#define ZPNP 1024    // fused z(768) + params(80) padded to 1024
#define NDEPTH 4
#define VOC 32000
#define NB 2
#define LL 1024
#define HD 3072
#define BL (NB*LL)

typedef __half fp16;

// ---------------- scratch (device globals) ----------------
__device__ __align__(16) float g_x[BL*EDIM];
__device__ __align__(16) float g_xn[BL*EDIM];
__device__ __align__(16) float g_zp[BL*ZPNP];
__device__ __align__(16) float g_dt[BL*EDIM];
__device__ __align__(16) float g_u[BL*EDIM];
__device__ __align__(16) float g_thid[NB*HD];
__device__ __align__(16) float g_temb[NB*EDIM];

// fp16 activation buffers
__device__ __align__(16) fp16 g_xnf[BL*EDIM];
__device__ __align__(16) fp16 g_yf[BL*EDIM];
__device__ __align__(16) fp16 g_hidf[BL*HD];

// fp16 hi/lo weight buffers (converted once per call)
__device__ __align__(16) fp16 g_wzp_h[NDEPTH*ZPNP*EDIM];
__device__ __align__(16) fp16 g_wzp_l[NDEPTH*ZPNP*EDIM];
__device__ __align__(16) fp16 g_wout_h[NDEPTH*EDIM*EDIM];
__device__ __align__(16) fp16 g_wout_l[NDEPTH*EDIM*EDIM];
__device__ __align__(16) fp16 g_wm1_h[NDEPTH*HD*EDIM];
__device__ __align__(16) fp16 g_wm1_l[NDEPTH*HD*EDIM];
__device__ __align__(16) fp16 g_wm2_h[NDEPTH*EDIM*HD];
__device__ __align__(16) fp16 g_wm2_l[NDEPTH*EDIM*HD];
__device__ __align__(16) fp16 g_whd_h[(size_t)VOC*EDIM];
__device__ __align__(16) fp16 g_whd_l[(size_t)VOC*EDIM];

// ---------------- helpers ----------------
__device__ __forceinline__ float siluf(float x) { return x / (1.0f + expf(-x)); }
__device__ __forceinline__ float geluf(float x) { return 0.5f * x * (1.0f + erff(x * 0.7071067811865476f)); }
__device__ __forceinline__ float softplusf(float x) { return (x > 20.0f) ? x : log1pf(expf(x)); }

__device__ __forceinline__ float warpsum(float v) {
    #pragma unroll
    for (int o = 16; o > 0; o >>= 1) v += __shfl_down_sync(0xffffffffu, v, o);
    return v;
}

__device__ __forceinline__ uint32_t smem_to_u32(const void* smem_ptr) {
    uint32_t addr;
    asm("{ .reg .u64 tmp; cvta.to.shared.u64 tmp, %1; cvt.u32.u64 %0, tmp; }"
        : "=r"(addr) : "l"(smem_ptr));
    return addr;
}

__device__ __forceinline__ void ldsm_x4(uint32_t& r0, uint32_t& r1, uint32_t& r2, uint32_t& r3,
                                        uint32_t addr) {
    asm volatile("ldmatrix.sync.aligned.m8n8.x4.shared.b16 {%0,%1,%2,%3}, [%4];"
                 : "=r"(r0), "=r"(r1), "=r"(r2), "=r"(r3) : "r"(addr));
}

__device__ __forceinline__ void mma16816h(float* c, const uint32_t* a, uint32_t b0, uint32_t b1) {
    asm volatile(
        "mma.sync.aligned.m16n8k16.row.col.f32.f16.f16.f32 "
        "{%0,%1,%2,%3}, {%4,%5,%6,%7}, {%8,%9}, {%0,%1,%2,%3};\n"
        : "+f"(c[0]), "+f"(c[1]), "+f"(c[2]), "+f"(c[3])
        : "r"(a[0]), "r"(a[1]), "r"(a[2]), "r"(a[3]), "r"(b0), "r"(b1));
}

#define CP_ASYNC16(dst, src) \
    asm volatile("cp.async.cg.shared.global [%0], [%1], 16;" :: "r"(dst), "l"(src) : "memory")
#define CP_COMMIT() asm volatile("cp.async.commit_group;" ::: "memory")
#define CP_WAIT(n)  asm volatile("cp.async.wait_group %0;" :: "n"(n) : "memory")

// ---------------- fused weight conversion + time_mlp1 (single launch) --------
#define NW1 ((size_t)NDEPTH*ZPNP*EDIM)
#define NW2 ((size_t)NDEPTH*EDIM*EDIM)
#define NW3 ((size_t)NDEPTH*HD*EDIM)
#define NW4 ((size_t)NDEPTH*EDIM*HD)
#define NW5 ((size_t)VOC*EDIM)
#define NWTOT (NW1+NW2+NW3+NW4+NW5)
#define NWB ((unsigned)((NWTOT + 255) / 256))
#define TM1B ((NB*HD)/8)

__global__ void cvt_tm1_kernel(
    const float* __restrict__ z_w, const float* __restrict__ p_w,
    const float* __restrict__ out_w, const float* __restrict__ mlp_w1,
    const float* __restrict__ mlp_w2, const float* __restrict__ head_w,
    fp16* __restrict__ wzph, fp16* __restrict__ wzpl,
    fp16* __restrict__ wouth, fp16* __restrict__ woutl,
    fp16* __restrict__ wm1h, fp16* __restrict__ wm1l,
    fp16* __restrict__ wm2h, fp16* __restrict__ wm2l,
    fp16* __restrict__ whdh, fp16* __restrict__ whdl,
    const int* __restrict__ timesteps,
    const float* __restrict__ time_w1, const float* __restrict__ time_b1,
    float* __restrict__ thid)
{
    if (blockIdx.x >= NWB) {
        int gw = (blockIdx.x - NWB) * 8 + (threadIdx.x >> 5);
        int ln = threadIdx.x & 31;
        if (gw >= NB * HD) return;
        int b = gw / HD, hh = gw % HD;
        const int half_ = EDIM / 2;
        float t = (float)timesteps[b];
        const float* w = time_w1 + (size_t)hh * EDIM;
        float s = 0.f;
        for (int k = ln; k < EDIM; k += 32) {
            int j = (k < half_) ? k : (k - half_);
            float freq = expf(-9.210340371976184f * (float)j / (float)half_);
            float arg = t * freq;
            float emb = (k < half_) ? sinf(arg) : cosf(arg);
            s += emb * w[k];
        }
        s = warpsum(s);
        if (ln == 0) { s += time_b1[hh]; thid[gw] = siluf(s); }
        return;
    }
    size_t i = (size_t)blockIdx.x * 256 + threadIdx.x;
    if (i >= NWTOT) return;
    float v; fp16 *ph, *pl; size_t j;
    if (i < NW1) {
        j = i;
        int c = j % EDIM;
        int r = (j / EDIM) % ZPNP;
        int d = j / ((size_t)ZPNP * EDIM);
        if (r < EDIM)           v = z_w[((size_t)d * EDIM + r) * EDIM + c];
        else if (r - EDIM < PD) v = p_w[((size_t)d * PD + (r - EDIM)) * EDIM + c];
        else                    v = 0.f;
        ph = wzph + j; pl = wzpl + j;
    } else if (i < NW1 + NW2) {
        j = i - NW1; v = out_w[j]; ph = wouth + j; pl = woutl + j;
    } else if (i < NW1 + NW2 + NW3) {
        j = i - NW1 - NW2; v = mlp_w1[j]; ph = wm1h + j; pl = wm1l + j;
    } else if (i < NW1 + NW2 + NW3 + NW4) {
        j = i - NW1 - NW2 - NW3; v = mlp_w2[j]; ph = wm2h + j; pl = wm2l + j;
    } else {
        j = i - NW1 - NW2 - NW3 - NW4; v = head_w[j]; ph = whdh + j; pl = whdl + j;
    }
    fp16 hv = __float2half_rn(v);
    *ph = hv;
    *pl = __float2half_rn(v - __half2float(hv));
}

__global__ void time_mlp2(const float* __restrict__ w2, const float* __restrict__ b2,
                          const float* __restrict__ thid, float* __restrict__ temb) {
    int gw = (blockIdx.x * blockDim.x + threadIdx.x) >> 5;
    int ln = threadIdx.x & 31;
    if (gw >= NB * EDIM) return;
    int b = gw / EDIM, e = gw % EDIM;
    const float* h = thid + b * HD;
    const float* w = w2 + (size_t)e * HD;
    float s = 0.f;
    for (int k = ln; k < HD; k += 32) s += h[k] * w[k];
    s = warpsum(s);
    if (ln == 0) temb[gw] = s + b2[e];
}

// ---------------- embed + layer-0 LN1 fused ----------------
__global__ void embed_ln1_kernel(const int* __restrict__ tokens,
                                 const float* __restrict__ tok_emb,
                                 const float* __restrict__ temb,
                                 const float* __restrict__ g, const float* __restrict__ bia,
                                 float* __restrict__ x, float* __restrict__ xn,
                                 fp16* __restrict__ of) {
    int row = blockIdx.x;
    int b = row / LL;
    int tok = tokens[row];
    const float* te = tok_emb + (size_t)tok * EDIM;
    const float* tb = temb + b * EDIM;
    __shared__ float sv[EDIM];
    float s = 0.f, s2 = 0.f;
    for (int e = threadIdx.x; e < EDIM; e += blockDim.x) {
        float v = te[e] + tb[e];
        sv[e] = v;
        x[(size_t)row * EDIM + e] = v;
        s += v; s2 += v * v;
    }
    __shared__ float sh1[8], sh2[8];
    __shared__ float smu, srs;
    int w = threadIdx.x >> 5, ln = threadIdx.x & 31;
    s = warpsum(s); s2 = warpsum(s2);
    if (ln == 0) { sh1[w] = s; sh2[w] = s2; }
    __syncthreads();
    if (threadIdx.x == 0) {
        float a = 0.f, c = 0.f;
        #pragma unroll
        for (int i = 0; i < 8; i++) { a += sh1[i]; c += sh2[i]; }
        float mu = a / EDIM;
        float var = c / EDIM - mu * mu;
        smu = mu; srs = rsqrtf(var + 1e-5f);
    }
    __syncthreads();
    float mu = smu, rs = srs;
    float* o = xn + (size_t)row * EDIM;
    fp16* pf = of + (size_t)row * EDIM;
    for (int e = threadIdx.x; e < EDIM; e += blockDim.x) {
        float v = (sv[e] - mu) * rs * g[e] + bia[e];
        o[e] = v;
        pf[e] = __float2half_rn(v);
    }
}

// ---------------- layernorm: fp32 out + fp16 out ----------------
__global__ void ln_kernel(const float* __restrict__ in, float* __restrict__ out,
                          fp16* __restrict__ of,
                          const float* __restrict__ g, const float* __restrict__ bia) {
    int row = blockIdx.x;
    const float* x = in + (size_t)row * EDIM;
    float s = 0.f, s2 = 0.f;
    for (int e = threadIdx.x; e < EDIM; e += blockDim.x) { float v = x[e]; s += v; s2 += v * v; }
    __shared__ float sh1[8], sh2[8];
    __shared__ float smu, srs;
    int w = threadIdx.x >> 5, ln = threadIdx.x & 31;
    s = warpsum(s); s2 = warpsum(s2);
    if (ln == 0) { sh1[w] = s; sh2[w] = s2; }
    __syncthreads();
    if (threadIdx.x == 0) {
        float a = 0.f, c = 0.f;
        #pragma unroll
        for (int i = 0; i < 8; i++) { a += sh1[i]; c += sh2[i]; }
        float mu = a / EDIM;
        float var = c / EDIM - mu * mu;
        smu = mu; srs = rsqrtf(var + 1e-5f);
    }
    __syncthreads();
    float mu = smu, rs = srs;
    float* o = out + (size_t)row * EDIM;
    fp16* pf = of + (size_t)row * EDIM;
    for (int e = threadIdx.x; e < EDIM; e += blockDim.x) {
        float v = (x[e] - mu) * rs * g[e] + bia[e];
        o[e] = v;
        pf[e] = __float2half_rn(v);
    }
}

// ---------------- depthwise causal conv + silu ----------------
__global__ void conv_silu(const float* __restrict__ xn, const float* __restrict__ w,
                          float* __restrict__ u) {
    int idx = blockIdx.x * blockDim.x + threadIdx.x;
    if (idx >= BL * EDIM) return;
    int e = idx % EDIM, bl = idx / EDIM, l = bl % LL, b = bl / LL;
    const float* base = xn + (size_t)b * LL * EDIM + e;
    float acc = 0.f;
    #pragma unroll
    for (int k = 0; k < KC; k++) {
        int ls = l - (KC - 1) + k;
        if (ls >= 0) acc += base[(size_t)ls * EDIM] * w[e * KC + k];
    }
    u[idx] = siluf(acc);
}

// ---------------- SSM scan: lag-2 pipelined reduction ----------------
// Thread per (b,e,n). Reduction over n (16 lanes) is split into two 2-shfl
// stages executed with a 1- and 2-iteration lag so the two dependent chains
// interleave and the critical path per step shrinks from ~4 to ~2 shfl stalls.
__global__ void scan_kernel(const float* __restrict__ Alog, const float* __restrict__ Dp,
                            const float* __restrict__ dt, const float* __restrict__ u,
                            const float* __restrict__ zp,
                            fp16* __restrict__ yf) {
    int g = blockIdx.x * blockDim.x + threadIdx.x;
    if (g >= NB * EDIM * NS) return;
    int n = g & (NS - 1);
    int pe = g >> 4;
    int e = pe % EDIM, b = pe / EDIM;

    float av = -expf(Alog[(size_t)e * NS + n]);
    float invA = 1.0f / (av + 1e-10f);
    bool smallA = fabsf(av) < 1e-5f;
    float D = Dp[e];

    const float* dtp = dt + (size_t)b * LL * EDIM + e;
    const float* up  = u  + (size_t)b * LL * EDIM + e;
    const float* zb  = zp + (size_t)b * LL * ZPNP;
    const float* cpp = zb + EDIM + RD + NS + n;
    const float* zgp = zb + e;
    fp16* yp = yf + (size_t)b * LL * EDIM + e;

    // prefetch for l
    float dtl = dtp[0];
    float ul  = up[0];
    float cv  = cpp[0];
    float zv  = (n == 0) ? zgp[0] : 0.f;

    float h = 0.f, dd = 0.f, uu = 0.f;
    float pend = 0.f, mid = 0.f;           // cur(l-1) raw, cur(l-2) stage1-done
    float u_h1 = 0.f, u_h2 = 0.f;
    float z_h1 = 0.f, z_h2 = 0.f;

    for (int l = 0; l < LL; l++) {
        float dtc = dtl, uc = ul, cc = cv, zc = zv;
        if (l + 1 < LL) {
            dtl = dtp[(size_t)(l + 1) * EDIM];
            ul  = up[(size_t)(l + 1) * EDIM];
            cv  = cpp[(size_t)(l + 1) * ZPNP];
            if (n == 0) zv = zgp[(size_t)(l + 1) * ZPNP];
        }
        float de = (l == 0) ? dtc : dd;
        float ue = (l == 0) ? uc  : uu;
        float At = __expf(de * av);
        float Bt = smallA ? de : (At - 1.0f) * invA;
        h = fmaf(At, h, Bt * ue);
        float cur = cc * h;

        // interleaved: stage1 of pend (l-1), stage2 of mid (l-2)
        float x1 = __shfl_xor_sync(0xffffffffu, pend, 1);
        float y1 = __shfl_xor_sync(0xffffffffu, mid, 4);
        pend += x1; mid += y1;
        float x2 = __shfl_xor_sync(0xffffffffu, pend, 2);
        float y2 = __shfl_xor_sync(0xffffffffu, mid, 8);
        pend += x2; mid += y2;
        if (n == 0 && l >= 2) {
            float v = (mid + u_h2 * D) * siluf(z_h2);
            yp[(size_t)(l - 2) * EDIM] = __float2half_rn(v);
        }
        mid = pend; pend = cur;
        u_h2 = u_h1; u_h1 = uc;
        z_h2 = z_h1; z_h1 = zc;
        dd = dtc; uu = uc;
    }
    // drain step 1: stage1 on pend (l=LL-1), stage2 on mid (l=LL-2)
    {
        float x1 = __shfl_xor_sync(0xffffffffu, pend, 1);
        float y1 = __shfl_xor_sync(0xffffffffu, mid, 4);
        pend += x1; mid += y1;
        float x2 = __shfl_xor_sync(0xffffffffu, pend, 2);
        float y2 = __shfl_xor_sync(0xffffffffu, mid, 8);
        pend += x2; mid += y2;
        if (n == 0) {
            float v = (mid + u_h2 * D) * siluf(z_h2);
            yp[(size_t)(LL - 2) * EDIM] = __float2half_rn(v);
        }
        mid = pend;
    }
    // drain step 2: stage2 on mid (l=LL-1)
    {
        float y1 = __shfl_xor_sync(0xffffffffu, mid, 4);
        mid += y1;
        float y2 = __shfl_xor_sync(0xffffffffu, mid, 8);
        mid += y2;
        if (n == 0) {
            float v = (mid + u_h1 * D) * siluf(z_h1);
            yp[(size_t)(LL - 1) * EDIM] = __float2half_rn(v);
        }
    }
}

// ---------------- SIMT GEMM (dt projection: K=48) -------
template<int ACT, bool BIAS, bool ACC>
__global__ void __launch_bounds__(256) gemm_tn(
    const float* __restrict__ A, int lda,
    const float* __restrict__ Bm, int ldb,
    const float* __restrict__ bias,
    float* __restrict__ C, int ldc,
    int M, int N, int K)
{
    __shared__ float As[8][132];
    __shared__ float Bs[8][132];
    int tid = threadIdx.x;
    int bm = blockIdx.y, bn = blockIdx.x;
    int tx = tid % 16, ty = tid / 16;

    float acc[8][8];
    #pragma unroll
    for (int i = 0; i < 8; i++)
        #pragma unroll
        for (int j = 0; j < 8; j++) acc[i][j] = 0.f;

    int ar = tid >> 1;
    int ak = (tid & 1) * 4;
    const float* Ab = A + (size_t)(bm * 128 + ar) * lda + ak;
    int brow = bn * 128 + ar;
    const float* Bb = Bm + (size_t)brow * ldb + ak;
    bool bvalid = brow < N;

    for (int k0 = 0; k0 < K; k0 += 8) {
        float4 av = *(const float4*)(Ab + k0);
        float4 bv = bvalid ? *(const float4*)(Bb + k0) : make_float4(0.f,0.f,0.f,0.f);
        As[ak+0][ar] = av.x; As[ak+1][ar] = av.y; As[ak+2][ar] = av.z; As[ak+3][ar] = av.w;
        Bs[ak+0][ar] = bv.x; Bs[ak+1][ar] = bv.y; Bs[ak+2][ar] = bv.z; Bs[ak+3][ar] = bv.w;
        __syncthreads();
        #pragma unroll
        for (int kk = 0; kk < 8; kk++) {
            float4 a0 = *(const float4*)(&As[kk][ty*8]);
            float4 a1 = *(const float4*)(&As[kk][ty*8+4]);
            float4 b0 = *(const float4*)(&Bs[kk][tx*8]);
            float4 b1 = *(const float4*)(&Bs[kk][tx*8+4]);
            float arf[8] = {a0.x,a0.y,a0.z,a0.w,a1.x,a1.y,a1.z,a1.w};
            float brf[8] = {b0.x,b0.y,b0.z,b0.w,b1.x,b1.y,b1.z,b1.w};
            #pragma unroll
            for (int i = 0; i < 8; i++)
                #pragma unroll
                for (int j = 0; j < 8; j++)
                    acc[i][j] = fmaf(arf[i], brf[j], acc[i][j]);
        }
        __syncthreads();
    }

    int row0 = bm * 128 + ty * 8;
    int col0 = bn * 128 + tx * 8;
    #pragma unroll
    for (int i = 0; i < 8; i++) {
        float* Crow = C + (size_t)(row0 + i) * ldc;
        #pragma unroll
        for (int jv = 0; jv < 8; jv += 4) {
            int col = col0 + jv;
            if (col < N) {
                float4 v = make_float4(acc[i][jv], acc[i][jv+1], acc[i][jv+2], acc[i][jv+3]);
                if (BIAS) {
                    v.x += bias[col]; v.y += bias[col+1]; v.z += bias[col+2]; v.w += bias[col+3];
                }
                if (ACT == 1) { v.x = softplusf(v.x); v.y = softplusf(v.y); v.z = softplusf(v.z); v.w = softplusf(v.w); }
                if (ACT == 2) { v.x = geluf(v.x); v.y = geluf(v.y); v.z = geluf(v.z); v.w = geluf(v.w); }
                if (ACC) {
                    float4 old = *(const float4*)(&Crow[col]);
                    v.x += old.x; v.y += old.y; v.z += old.z; v.w += old.w;
                }
                *(float4*)(&Crow[col]) = v;
            }
        }
    }
}

// ================= fp16 2-term mma GEMM: 64x64 tile, 4 warps, 3-stage ========
#define GSTAGE 12288
#define GSMEM  (3*GSTAGE)

__device__ __forceinline__ void g_load_stage(
    uint32_t st, const fp16* __restrict__ A,
    const fp16* __restrict__ Bh, const fp16* __restrict__ Bl,
    int K, int koff, int tid)
{
    int r = tid >> 1;                // 0..63
    int gb = (tid & 1) * 2;
    size_t ro = (size_t)r * K + koff;
    #pragma unroll
    for (int gi = 0; gi < 2; gi++) {
        int g = gb + gi;
        uint32_t so = (uint32_t)(r * 64 + ((g ^ ((r >> 1) & 3)) << 4));
        CP_ASYNC16(st + so,          A  + ro + g * 8);
        CP_ASYNC16(st + 4096 + so,   Bh + ro + g * 8);
        CP_ASYNC16(st + 8192 + so,   Bl + ro + g * 8);
    }
}

template<int ACT, bool BIAS, int OUT>
__global__ void __launch_bounds__(128, 6) gemm_f16(
    const fp16* __restrict__ A,
    const fp16* __restrict__ Bh, const fp16* __restrict__ Bl,
    int K, const float* __restrict__ bias,
    float* __restrict__ C, fp16* __restrict__ Cf,
    int ldc, int nmax)
{
    extern __shared__ __align__(16) unsigned char smem_raw[];
    uint32_t sb = smem_to_u32(smem_raw);

    int tid = threadIdx.x;
    int wid = tid >> 5, lid = tid & 31;
    int wm = wid & 1, wn = wid >> 1;     // 2(m) x 2(n)

    const fp16* A0  = A  + (size_t)(blockIdx.x * 64) * K;
    const fp16* Bh0 = Bh + (size_t)(blockIdx.y * 64) * K;
    const fp16* Bl0 = Bl + (size_t)(blockIdx.y * 64) * K;

    float acc[2][4][4];
    #pragma unroll
    for (int i = 0; i < 2; i++)
        #pragma unroll
        for (int j = 0; j < 4; j++)
            #pragma unroll
            for (int q = 0; q < 4; q++) acc[i][j][q] = 0.f;

    int NC = K / 32;
    g_load_stage(sb, A0, Bh0, Bl0, K, 0, tid);
    CP_COMMIT();
    g_load_stage(sb + GSTAGE, A0, Bh0, Bl0, K, 32, tid);
    CP_COMMIT();

    for (int c = 0; c < NC; c++) {
        if (c + 1 < NC) { CP_WAIT(1); } else { CP_WAIT(0); }
        __syncthreads();
        if (c + 2 < NC) {
            g_load_stage(sb + ((c + 2) % 3) * GSTAGE, A0, Bh0, Bl0, K, (c + 2) * 32, tid);
            CP_COMMIT();
        }

        uint32_t st = sb + (c % 3) * GSTAGE;
        uint32_t sA = st, sBh = st + 4096, sBl = st + 8192;

        #pragma unroll
        for (int ks = 0; ks < 2; ks++) {
            int kch = 2 * ks + (lid >> 4);
            uint32_t bh[2][4], bl_[2][4];
            #pragma unroll
            for (int j2 = 0; j2 < 2; j2++) {
                int mrow = wn * 32 + j2 * 16 + ((lid >> 3) & 1) * 8 + (lid & 7);
                uint32_t off = (uint32_t)(mrow * 64)
                             + (((uint32_t)kch ^ (((uint32_t)mrow >> 1) & 3u)) << 4);
                ldsm_x4(bh[j2][0], bh[j2][1], bh[j2][2], bh[j2][3], sBh + off);
                ldsm_x4(bl_[j2][0], bl_[j2][1], bl_[j2][2], bl_[j2][3], sBl + off);
            }
            #pragma unroll
            for (int i = 0; i < 2; i++) {
                int arow = wm * 32 + i * 16 + (lid & 15);
                uint32_t off = (uint32_t)(arow * 64)
                             + (((uint32_t)kch ^ (((uint32_t)arow >> 1) & 3u)) << 4);
                uint32_t ah[4];
                ldsm_x4(ah[0], ah[1], ah[2], ah[3], sA + off);
                #pragma unroll
                for (int j = 0; j < 4; j++) {
                    int j2 = j >> 1, js = j & 1;
                    mma16816h(acc[i][j], ah, bh[j2][js], bh[j2][2 + js]);
                    mma16816h(acc[i][j], ah, bl_[j2][js], bl_[j2][2 + js]);
                }
            }
        }
    }

    int lr = lid >> 2;
    int lc = (lid & 3) * 2;
    #pragma unroll
    for (int i = 0; i < 2; i++) {
        int row = blockIdx.x * 64 + wm * 32 + i * 16 + lr;
        #pragma unroll
        for (int j = 0; j < 4; j++) {
            int col0 = blockIdx.y * 64 + wn * 32 + j * 8 + lc;
            if (col0 < nmax) {
                #pragma unroll
                for (int half = 0; half < 2; half++) {
                    int rr = row + half * 8;
                    float v0 = acc[i][j][half * 2 + 0];
                    float v1 = acc[i][j][half * 2 + 1];
                    if (BIAS) { v0 += bias[col0]; v1 += bias[col0 + 1]; }
                    if (ACT == 1) { v0 = softplusf(v0); v1 = softplusf(v1); }
                    if (ACT == 2) { v0 = geluf(v0); v1 = geluf(v1); }
                    if (OUT == 2) {
                        __half2* pf = (__half2*)(Cf + (size_t)rr * ldc + col0);
                        *pf = __floats2half2_rn(v0, v1);
                    } else {
                        float* cp = C + (size_t)rr * ldc + col0;
                        if (OUT == 1) {
                            float2 old = *(const float2*)cp;
                            v0 += old.x; v1 += old.y;
                        }
                        *(float2*)cp = make_float2(v0, v1);
                    }
                }
            }
        }
    }
}

// ================= fp16 2-term head GEMM: 128x128, 8 warps, 3-stage ==========
#define HSTAGE 24576
#define HSMEM  (3*HSTAGE)

__device__ __forceinline__ void h_load_stage(
    uint32_t st, const fp16* __restrict__ A,
    const fp16* __restrict__ Bh, const fp16* __restrict__ Bl,
    int K, int koff, int tid)
{
    int r = tid >> 1;
    int gb = (tid & 1) * 2;
    size_t ro = (size_t)r * K + koff;
    #pragma unroll
    for (int gi = 0; gi < 2; gi++) {
        int g = gb + gi;
        uint32_t so = (uint32_t)(r * 64 + ((g ^ ((r >> 1) & 3)) << 4));
        CP_ASYNC16(st + so,          A  + ro + g * 8);
        CP_ASYNC16(st + 8192 + so,   Bh + ro + g * 8);
        CP_ASYNC16(st + 16384 + so,  Bl + ro + g * 8);
    }
}

__global__ void __launch_bounds__(256, 2) gemm_hd(
    const fp16* __restrict__ A,
    const fp16* __restrict__ Bh, const fp16* __restrict__ Bl,
    int K, const float* __restrict__ bias,
    float* __restrict__ C, int ldc)
{
    extern __shared__ __align__(16) unsigned char smem_raw[];
    uint32_t sb = smem_to_u32(smem_raw);

    int tid = threadIdx.x;
    int wid = tid >> 5, lid = tid & 31;
    int wm = wid & 1, wn = wid >> 1;

    const fp16* A0  = A  + (size_t)(blockIdx.x * 128) * K;
    const fp16* Bh0 = Bh + (size_t)(blockIdx.y * 128) * K;
    const fp16* Bl0 = Bl + (size_t)(blockIdx.y * 128) * K;

    float acc[4][4][4];
    #pragma unroll
    for (int i = 0; i < 4; i++)
        #pragma unroll
        for (int j = 0; j < 4; j++)
            #pragma unroll
            for (int q = 0; q < 4; q++) acc[i][j][q] = 0.f;

    int NC = K / 32;
    h_load_stage(sb, A0, Bh0, Bl0, K, 0, tid);
    CP_COMMIT();
    h_load_stage(sb + HSTAGE, A0, Bh0, Bl0, K, 32, tid);
    CP_COMMIT();

    for (int c = 0; c < NC; c++) {
        if (c + 1 < NC) { CP_WAIT(1); } else { CP_WAIT(0); }
        __syncthreads();
        if (c + 2 < NC) {
            h_load_stage(sb + ((c + 2) % 3) * HSTAGE, A0, Bh0, Bl0, K, (c + 2) * 32, tid);
            CP_COMMIT();
        }

        uint32_t st = sb + (c % 3) * HSTAGE;
        uint32_t sA = st, sBh = st + 8192, sBl = st + 16384;

        #pragma unroll
        for (int ks = 0; ks < 2; ks++) {
            int kch = 2 * ks + (lid >> 4);
            uint32_t bh[2][4], bl_[2][4];
            #pragma unroll
            for (int j2 = 0; j2 < 2; j2++) {
                int mrow = wn * 32 + j2 * 16 + ((lid >> 3) & 1) * 8 + (lid & 7);
                uint32_t off = (uint32_t)(mrow * 64)
                             + (((uint32_t)kch ^ (((uint32_t)mrow >> 1) & 3u)) << 4);
                ldsm_x4(bh[j2][0], bh[j2][1], bh[j2][2], bh[j2][3], sBh + off);
                ldsm_x4(bl_[j2][0], bl_[j2][1], bl_[j2][2], bl_[j2][3], sBl + off);
            }
            #pragma unroll
            for (int i = 0; i < 4; i++) {
                int arow = wm * 64 + i * 16 + (lid & 15);
                uint32_t off = (uint32_t)(arow * 64)
                             + (((uint32_t)kch ^ (((uint32_t)arow >> 1) & 3u)) << 4);
                uint32_t ah[4];
                ldsm_x4(ah[0], ah[1], ah[2], ah[3], sA + off);
                #pragma unroll
                for (int j = 0; j < 4; j++) {
                    int j2 = j >> 1, js = j & 1;
                    mma16816h(acc[i][j], ah, bh[j2][js], bh[j2][2 + js]);
                    mma16816h(acc[i][j], ah, bl_[j2][js], bl_[j2][2 + js]);
                }
            }
        }
    }

    int lr = lid >> 2;
    int lc = (lid & 3) * 2;
    #pragma unroll
    for (int i = 0; i < 4; i++) {
        int row = blockIdx.x * 128 + wm * 64 + i * 16 + lr;
        #pragma unroll
        for (int j = 0; j < 4; j++) {
            int col0 = blockIdx.y * 128 + wn * 32 + j * 8 + lc;
            #pragma unroll
            for (int half = 0; half < 2; half++) {
                int rr = row + half * 8;
                float v0 = acc[i][j][half * 2 + 0] + bias[col0];
                float v1 = acc[i][j][half * 2 + 1] + bias[col0 + 1];
                *(float2*)(C + (size_t)rr * ldc + col0) = make_float2(v0, v1);
            }
        }
    }
}

// ---------------- launch ----------------
extern "C" void kernel_launch(void* const* d_in, const int* in_sizes, int n_in,
                              void* d_out, int out_size) {
    const int*   tokens    = (const int*)  d_in[0];
    const int*   timesteps = (const int*)  d_in[1];
    const float* tok_emb   = (const float*)d_in[2];
    const float* time_w1   = (const float*)d_in[3];
    const float* time_b1   = (const float*)d_in[4];
    const float* time_w2   = (const float*)d_in[5];
    const float* time_b2   = (const float*)d_in[6];
    const float* ln1_g     = (const float*)d_in[7];
    const float* ln1_b     = (const float*)d_in[8];
    const float* z_w       = (const float*)d_in[9];
    const float* p_w       = (const float*)d_in[10];
    const float* conv_w    = (const float*)d_in[11];
    const float* dtp_w     = (const float*)d_in[12];
    const float* dtp_b     = (const float*)d_in[13];
    const float* A_log     = (const float*)d_in[14];
    const float* D_param   = (const float*)d_in[15];
    const float* out_w     = (const float*)d_in[16];
    const float* ln2_g     = (const float*)d_in[17];
    const float* ln2_b     = (const float*)d_in[18];
    const float* mlp_w1    = (const float*)d_in[19];
    const float* mlp_b1    = (const float*)d_in[20];
    const float* mlp_w2    = (const float*)d_in[21];
    const float* mlp_b2    = (const float*)d_in[22];
    const float* lnout_g   = (const float*)d_in[23];
    const float* lnout_b   = (const float*)d_in[24];
    const float* head_w    = (const float*)d_in[25];
    const float* head_b    = (const float*)d_in[26];

    #define GETP(sym, var, type) void* _p_##var; cudaGetSymbolAddress(&_p_##var, sym); type* var = (type*)_p_##var
    GETP(g_x, bx, float);       GETP(g_xn, bxn, float);
    GETP(g_zp, bzp, float);     GETP(g_dt, bdt, float);
    GETP(g_u, bu, float);
    GETP(g_thid, bthid, float); GETP(g_temb, btemb, float);
    GETP(g_xnf, bxnf, fp16);    GETP(g_yf, byf, fp16);     GETP(g_hidf, bhidf, fp16);
    GETP(g_wzp_h, wzph, fp16);  GETP(g_wzp_l, wzpl, fp16);
    GETP(g_wout_h, wouth, fp16);GETP(g_wout_l, woutl, fp16);
    GETP(g_wm1_h, wm1h, fp16);  GETP(g_wm1_l, wm1l, fp16);
    GETP(g_wm2_h, wm2h, fp16);  GETP(g_wm2_l, wm2l, fp16);
    GETP(g_whd_h, whdh, fp16);  GETP(g_whd_l, whdl, fp16);
    #undef GETP

    cudaFuncSetAttribute(gemm_f16<0,false,0>, cudaFuncAttributeMaxDynamicSharedMemorySize, GSMEM);
    cudaFuncSetAttribute(gemm_f16<0,false,1>, cudaFuncAttributeMaxDynamicSharedMemorySize, GSMEM);
    cudaFuncSetAttribute(gemm_f16<2,true, 2>, cudaFuncAttributeMaxDynamicSharedMemorySize, GSMEM);
    cudaFuncSetAttribute(gemm_f16<0,true, 1>, cudaFuncAttributeMaxDynamicSharedMemorySize, GSMEM);
    cudaFuncSetAttribute(gemm_hd, cudaFuncAttributeMaxDynamicSharedMemorySize, HSMEM);

    // 1: fused weight conversion + time_mlp1
    cvt_tm1_kernel<<<NWB + TM1B, 256>>>(
        z_w, p_w, out_w, mlp_w1, mlp_w2, head_w,
        wzph, wzpl, wouth, woutl, wm1h, wm1l, wm2h, wm2l, whdh, whdl,
        timesteps, time_w1, time_b1, bthid);
    // 2: time_mlp2
    time_mlp2<<<(NB*EDIM*32 + 255)/256, 256>>>(time_w2, time_b2, bthid, btemb);
    // 3: embed + layer-0 LN1
    embed_ln1_kernel<<<BL, 256>>>(tokens, tok_emb, btemb, ln1_g, ln1_b,
                                  bx, bxn, bxnf);

    for (int i = 0; i < NDEPTH; i++) {
        const fp16* wzph_i = wzph + (size_t)i * ZPNP * EDIM;
        const fp16* wzpl_i = wzpl + (size_t)i * ZPNP * EDIM;
        const fp16* wouth_i = wouth + (size_t)i * EDIM * EDIM;
        const fp16* woutl_i = woutl + (size_t)i * EDIM * EDIM;
        const fp16* wm1h_i = wm1h + (size_t)i * HD * EDIM;
        const fp16* wm1l_i = wm1l + (size_t)i * HD * EDIM;
        const fp16* wm2h_i = wm2h + (size_t)i * EDIM * HD;
        const fp16* wm2l_i = wm2l + (size_t)i * EDIM * HD;
        const float* cwi  = conv_w + (size_t)i * EDIM * KC;
        const float* dtwi = dtp_w + (size_t)i * EDIM * RD;
        const float* dtbi = dtp_b + (size_t)i * EDIM;
        const float* ali  = A_log + (size_t)i * EDIM * NS;
        const float* dpi  = D_param + (size_t)i * EDIM;
        const float* b1i  = mlp_b1 + (size_t)i * HD;
        const float* b2i  = mlp_b2 + (size_t)i * EDIM;

        if (i > 0)
            ln_kernel<<<BL, 256>>>(bx, bxn, bxnf, ln1_g + i*EDIM, ln1_b + i*EDIM);
        // 4 (first iter): zp GEMM — in ncu capture window
        gemm_f16<0,false,0><<<dim3(BL/64, ZPNP/64), 128, GSMEM>>>(
            bxnf, wzph_i, wzpl_i, EDIM, nullptr, bzp, nullptr, ZPNP, ZPNP);
        gemm_tn<1,true,false><<<dim3(EDIM/128, BL/128), 256>>>(
            bzp + EDIM, ZPNP, dtwi, RD, dtbi, bdt, EDIM, BL, EDIM, RD);
        conv_silu<<<(BL*EDIM + 255)/256, 256>>>(bxn, cwi, bu);
        scan_kernel<<<(NB*EDIM*NS + 255)/256, 256>>>(ali, dpi, bdt, bu, bzp, byf);
        gemm_f16<0,false,1><<<dim3(BL/64, EDIM/64), 128, GSMEM>>>(
            byf, wouth_i, woutl_i, EDIM, nullptr, bx, nullptr, EDIM, EDIM);
        ln_kernel<<<BL, 256>>>(bx, bxn, bxnf, ln2_g + i*EDIM, ln2_b + i*EDIM);
        gemm_f16<2,true,2><<<dim3(BL/64, HD/64), 128, GSMEM>>>(
            bxnf, wm1h_i, wm1l_i, EDIM, b1i, nullptr, bhidf, HD, HD);
        gemm_f16<0,true,1><<<dim3(BL/64, EDIM/64), 128, GSMEM>>>(
            bhidf, wm2h_i, wm2l_i, HD, b2i, bx, nullptr, EDIM, EDIM);
    }

    ln_kernel<<<BL, 256>>>(bx, bxn, bxnf, lnout_g, lnout_b);
    gemm_hd<<<dim3(BL/128, VOC/128), 256, HSMEM>>>(
        bxnf, whdh, whdl, EDIM, head_b, (float*)d_out, VOC);
}

// round 12
// speedup vs baseline: 1.4013x; 1.1947x over previous
#include <cuda_runtime.h>
#include <cuda_bf16.h>
#include <cuda_fp16.h>
#include <math.h>
#include <stdint.h>

#define EDIM 768
#define NS 16
#define KC 4
#define RD 48
#define PD 80        // R + 2N
#define ZPNP 1024    // fused z(768) + params(80) padded to 1024
#define KDT 64       // dt projection K padded 48 -> 64
#define NDEPTH 4
#define VOC 32000
#define NB 2
#define LL 1024
#define HD 3072
#define BL (NB*LL)

typedef __half fp16;

// ---------------- scratch (device globals) ----------------
__device__ __align__(16) float g_x[BL*EDIM];
__device__ __align__(16) float g_xn[BL*EDIM];
__device__ __align__(16) float g_zp[BL*ZPNP];
__device__ __align__(16) float g_dt[BL*EDIM];
__device__ __align__(16) float g_thid[NB*HD];
__device__ __align__(16) float g_temb[NB*EDIM];

// fp16 activation buffers
__device__ __align__(16) fp16 g_xnf[BL*EDIM];
__device__ __align__(16) fp16 g_zpf[BL*ZPNP];
__device__ __align__(16) fp16 g_yf[BL*EDIM];
__device__ __align__(16) fp16 g_hidf[BL*HD];

// fp16 hi/lo weight buffers (converted once per call)
__device__ __align__(16) fp16 g_wzp_h[NDEPTH*ZPNP*EDIM];
__device__ __align__(16) fp16 g_wzp_l[NDEPTH*ZPNP*EDIM];
__device__ __align__(16) fp16 g_wout_h[NDEPTH*EDIM*EDIM];
__device__ __align__(16) fp16 g_wout_l[NDEPTH*EDIM*EDIM];
__device__ __align__(16) fp16 g_wm1_h[NDEPTH*HD*EDIM];
__device__ __align__(16) fp16 g_wm1_l[NDEPTH*HD*EDIM];
__device__ __align__(16) fp16 g_wm2_h[NDEPTH*EDIM*HD];
__device__ __align__(16) fp16 g_wm2_l[NDEPTH*EDIM*HD];
__device__ __align__(16) fp16 g_whd_h[(size_t)VOC*EDIM];
__device__ __align__(16) fp16 g_whd_l[(size_t)VOC*EDIM];
__device__ __align__(16) fp16 g_wdt_h[NDEPTH*EDIM*KDT];
__device__ __align__(16) fp16 g_wdt_l[NDEPTH*EDIM*KDT];

// ---------------- helpers ----------------
__device__ __forceinline__ float siluf(float x) { return x / (1.0f + expf(-x)); }
__device__ __forceinline__ float geluf(float x) { return 0.5f * x * (1.0f + erff(x * 0.7071067811865476f)); }
__device__ __forceinline__ float softplusf(float x) { return (x > 20.0f) ? x : log1pf(expf(x)); }

__device__ __forceinline__ float warpsum(float v) {
    #pragma unroll
    for (int o = 16; o > 0; o >>= 1) v += __shfl_down_sync(0xffffffffu, v, o);
    return v;
}

__device__ __forceinline__ uint32_t smem_to_u32(const void* smem_ptr) {
    uint32_t addr;
    asm("{ .reg .u64 tmp; cvta.to.shared.u64 tmp, %1; cvt.u32.u64 %0, tmp; }"
        : "=r"(addr) : "l"(smem_ptr));
    return addr;
}

__device__ __forceinline__ void ldsm_x4(uint32_t& r0, uint32_t& r1, uint32_t& r2, uint32_t& r3,
                                        uint32_t addr) {
    asm volatile("ldmatrix.sync.aligned.m8n8.x4.shared.b16 {%0,%1,%2,%3}, [%4];"
                 : "=r"(r0), "=r"(r1), "=r"(r2), "=r"(r3) : "r"(addr));
}

__device__ __forceinline__ void mma16816h(float* c, const uint32_t* a, uint32_t b0, uint32_t b1) {
    asm volatile(
        "mma.sync.aligned.m16n8k16.row.col.f32.f16.f16.f32 "
        "{%0,%1,%2,%3}, {%4,%5,%6,%7}, {%8,%9}, {%0,%1,%2,%3};\n"
        : "+f"(c[0]), "+f"(c[1]), "+f"(c[2]), "+f"(c[3])
        : "r"(a[0]), "r"(a[1]), "r"(a[2]), "r"(a[3]), "r"(b0), "r"(b1));
}

#define CP_ASYNC16(dst, src) \
    asm volatile("cp.async.cg.shared.global [%0], [%1], 16;" :: "r"(dst), "l"(src) : "memory")
#define CP_COMMIT() asm volatile("cp.async.commit_group;" ::: "memory")
#define CP_WAIT(n)  asm volatile("cp.async.wait_group %0;" :: "n"(n) : "memory")

// ---------------- fused weight conversion + time_mlp1 (single launch) --------
#define NW1 ((size_t)NDEPTH*ZPNP*EDIM)
#define NW2 ((size_t)NDEPTH*EDIM*EDIM)
#define NW3 ((size_t)NDEPTH*HD*EDIM)
#define NW4 ((size_t)NDEPTH*EDIM*HD)
#define NW5 ((size_t)VOC*EDIM)
#define NW6 ((size_t)NDEPTH*EDIM*KDT)
#define NWTOT (NW1+NW2+NW3+NW4+NW5+NW6)
#define NWB ((unsigned)((NWTOT + 255) / 256))
#define TM1B ((NB*HD)/8)

__global__ void cvt_tm1_kernel(
    const float* __restrict__ z_w, const float* __restrict__ p_w,
    const float* __restrict__ out_w, const float* __restrict__ mlp_w1,
    const float* __restrict__ mlp_w2, const float* __restrict__ head_w,
    const float* __restrict__ dtp_w,
    fp16* __restrict__ wzph, fp16* __restrict__ wzpl,
    fp16* __restrict__ wouth, fp16* __restrict__ woutl,
    fp16* __restrict__ wm1h, fp16* __restrict__ wm1l,
    fp16* __restrict__ wm2h, fp16* __restrict__ wm2l,
    fp16* __restrict__ whdh, fp16* __restrict__ whdl,
    fp16* __restrict__ wdth, fp16* __restrict__ wdtl,
    const int* __restrict__ timesteps,
    const float* __restrict__ time_w1, const float* __restrict__ time_b1,
    float* __restrict__ thid)
{
    if (blockIdx.x >= NWB) {
        int gw = (blockIdx.x - NWB) * 8 + (threadIdx.x >> 5);
        int ln = threadIdx.x & 31;
        if (gw >= NB * HD) return;
        int b = gw / HD, hh = gw % HD;
        const int half_ = EDIM / 2;
        float t = (float)timesteps[b];
        const float* w = time_w1 + (size_t)hh * EDIM;
        float s = 0.f;
        for (int k = ln; k < EDIM; k += 32) {
            int j = (k < half_) ? k : (k - half_);
            float freq = expf(-9.210340371976184f * (float)j / (float)half_);
            float arg = t * freq;
            float emb = (k < half_) ? sinf(arg) : cosf(arg);
            s += emb * w[k];
        }
        s = warpsum(s);
        if (ln == 0) { s += time_b1[hh]; thid[gw] = siluf(s); }
        return;
    }
    size_t i = (size_t)blockIdx.x * 256 + threadIdx.x;
    if (i >= NWTOT) return;
    float v; fp16 *ph, *pl; size_t j;
    if (i < NW1) {
        j = i;
        int c = j % EDIM;
        int r = (j / EDIM) % ZPNP;
        int d = j / ((size_t)ZPNP * EDIM);
        if (r < EDIM)           v = z_w[((size_t)d * EDIM + r) * EDIM + c];
        else if (r - EDIM < PD) v = p_w[((size_t)d * PD + (r - EDIM)) * EDIM + c];
        else                    v = 0.f;
        ph = wzph + j; pl = wzpl + j;
    } else if (i < NW1 + NW2) {
        j = i - NW1; v = out_w[j]; ph = wouth + j; pl = woutl + j;
    } else if (i < NW1 + NW2 + NW3) {
        j = i - NW1 - NW2; v = mlp_w1[j]; ph = wm1h + j; pl = wm1l + j;
    } else if (i < NW1 + NW2 + NW3 + NW4) {
        j = i - NW1 - NW2 - NW3; v = mlp_w2[j]; ph = wm2h + j; pl = wm2l + j;
    } else if (i < NW1 + NW2 + NW3 + NW4 + NW5) {
        j = i - NW1 - NW2 - NW3 - NW4; v = head_w[j]; ph = whdh + j; pl = whdl + j;
    } else {
        j = i - NW1 - NW2 - NW3 - NW4 - NW5;
        int k = j % KDT;
        int e = (j / KDT) % EDIM;
        int d = j / ((size_t)EDIM * KDT);
        v = (k < RD) ? dtp_w[((size_t)d * EDIM + e) * RD + k] : 0.f;
        ph = wdth + j; pl = wdtl + j;
    }
    fp16 hv = __float2half_rn(v);
    *ph = hv;
    *pl = __float2half_rn(v - __half2float(hv));
}

__global__ void time_mlp2(const float* __restrict__ w2, const float* __restrict__ b2,
                          const float* __restrict__ thid, float* __restrict__ temb) {
    int gw = (blockIdx.x * blockDim.x + threadIdx.x) >> 5;
    int ln = threadIdx.x & 31;
    if (gw >= NB * EDIM) return;
    int b = gw / EDIM, e = gw % EDIM;
    const float* h = thid + b * HD;
    const float* w = w2 + (size_t)e * HD;
    float s = 0.f;
    for (int k = ln; k < HD; k += 32) s += h[k] * w[k];
    s = warpsum(s);
    if (ln == 0) temb[gw] = s + b2[e];
}

// ---------------- embed + layer-0 LN1 fused ----------------
__global__ void embed_ln1_kernel(const int* __restrict__ tokens,
                                 const float* __restrict__ tok_emb,
                                 const float* __restrict__ temb,
                                 const float* __restrict__ g, const float* __restrict__ bia,
                                 float* __restrict__ x, float* __restrict__ xn,
                                 fp16* __restrict__ of) {
    int row = blockIdx.x;
    int b = row / LL;
    int tok = tokens[row];
    const float* te = tok_emb + (size_t)tok * EDIM;
    const float* tb = temb + b * EDIM;
    __shared__ float sv[EDIM];
    float s = 0.f, s2 = 0.f;
    for (int e = threadIdx.x; e < EDIM; e += blockDim.x) {
        float v = te[e] + tb[e];
        sv[e] = v;
        x[(size_t)row * EDIM + e] = v;
        s += v; s2 += v * v;
    }
    __shared__ float sh1[8], sh2[8];
    __shared__ float smu, srs;
    int w = threadIdx.x >> 5, ln = threadIdx.x & 31;
    s = warpsum(s); s2 = warpsum(s2);
    if (ln == 0) { sh1[w] = s; sh2[w] = s2; }
    __syncthreads();
    if (threadIdx.x == 0) {
        float a = 0.f, c = 0.f;
        #pragma unroll
        for (int i = 0; i < 8; i++) { a += sh1[i]; c += sh2[i]; }
        float mu = a / EDIM;
        float var = c / EDIM - mu * mu;
        smu = mu; srs = rsqrtf(var + 1e-5f);
    }
    __syncthreads();
    float mu = smu, rs = srs;
    float* o = xn + (size_t)row * EDIM;
    fp16* pf = of + (size_t)row * EDIM;
    for (int e = threadIdx.x; e < EDIM; e += blockDim.x) {
        float v = (sv[e] - mu) * rs * g[e] + bia[e];
        o[e] = v;
        pf[e] = __float2half_rn(v);
    }
}

// ---------------- layernorm: fp32 out + fp16 out ----------------
__global__ void ln_kernel(const float* __restrict__ in, float* __restrict__ out,
                          fp16* __restrict__ of,
                          const float* __restrict__ g, const float* __restrict__ bia) {
    int row = blockIdx.x;
    const float* x = in + (size_t)row * EDIM;
    float s = 0.f, s2 = 0.f;
    for (int e = threadIdx.x; e < EDIM; e += blockDim.x) { float v = x[e]; s += v; s2 += v * v; }
    __shared__ float sh1[8], sh2[8];
    __shared__ float smu, srs;
    int w = threadIdx.x >> 5, ln = threadIdx.x & 31;
    s = warpsum(s); s2 = warpsum(s2);
    if (ln == 0) { sh1[w] = s; sh2[w] = s2; }
    __syncthreads();
    if (threadIdx.x == 0) {
        float a = 0.f, c = 0.f;
        #pragma unroll
        for (int i = 0; i < 8; i++) { a += sh1[i]; c += sh2[i]; }
        float mu = a / EDIM;
        float var = c / EDIM - mu * mu;
        smu = mu; srs = rsqrtf(var + 1e-5f);
    }
    __syncthreads();
    float mu = smu, rs = srs;
    float* o = out + (size_t)row * EDIM;
    fp16* pf = of + (size_t)row * EDIM;
    for (int e = threadIdx.x; e < EDIM; e += blockDim.x) {
        float v = (x[e] - mu) * rs * g[e] + bia[e];
        o[e] = v;
        pf[e] = __float2half_rn(v);
    }
}

// ---------------- SSM scan: fused conv+silu, batch-4 prefetch, lag-2 reduce ---
// Thread per (b,e,n). u computed inline from xn rolling window (causal conv).
__global__ void __launch_bounds__(128) scan_kernel(
    const float* __restrict__ Alog, const float* __restrict__ Dp,
    const float* __restrict__ dt, const float* __restrict__ xn,
    const float* __restrict__ conv_w,
    const float* __restrict__ zp, fp16* __restrict__ yf) {
    int g = blockIdx.x * blockDim.x + threadIdx.x;
    if (g >= NB * EDIM * NS) return;
    int n = g & (NS - 1);
    int pe = g >> 4;
    int e = pe % EDIM, b = pe / EDIM;

    float av = -expf(Alog[(size_t)e * NS + n]);
    float invA = 1.0f / (av + 1e-10f);
    bool smallA = fabsf(av) < 1e-5f;
    float D = Dp[e];
    float w0 = conv_w[e * KC + 0], w1 = conv_w[e * KC + 1];
    float w2 = conv_w[e * KC + 2], w3 = conv_w[e * KC + 3];

    const float* dtp = dt + (size_t)b * LL * EDIM + e;
    const float* xp  = xn + (size_t)b * LL * EDIM + e;
    const float* zb  = zp + (size_t)b * LL * ZPNP;
    const float* cpp = zb + EDIM + RD + NS + n;
    const float* zgp = zb + e;
    fp16* yp = yf + (size_t)b * LL * EDIM + e;

    float bx4[4], bdt4[4], bc4[4], bz4[4];
    #pragma unroll
    for (int j = 0; j < 4; j++) {
        bx4[j]  = xp[(size_t)j * EDIM];
        bdt4[j] = dtp[(size_t)j * EDIM];
        bc4[j]  = cpp[(size_t)j * ZPNP];
        bz4[j]  = (n == 0) ? zgp[(size_t)j * ZPNP] : 0.f;
    }

    float xm1 = 0.f, xm2 = 0.f, xm3 = 0.f;
    float h = 0.f, dd = 0.f, uu = 0.f;
    float pend = 0.f, mid = 0.f;
    float u_h1 = 0.f, u_h2 = 0.f;
    float z_h1 = 0.f, z_h2 = 0.f;

    for (int lb = 0; lb < LL; lb += 4) {
        float nx4[4], ndt4[4], nc4[4], nz4[4];
        if (lb + 4 < LL) {
            #pragma unroll
            for (int j = 0; j < 4; j++) {
                size_t l1 = (size_t)(lb + 4 + j);
                nx4[j]  = xp[l1 * EDIM];
                ndt4[j] = dtp[l1 * EDIM];
                nc4[j]  = cpp[l1 * ZPNP];
                nz4[j]  = (n == 0) ? zgp[l1 * ZPNP] : 0.f;
            }
        } else {
            #pragma unroll
            for (int j = 0; j < 4; j++) { nx4[j]=0.f; ndt4[j]=0.f; nc4[j]=0.f; nz4[j]=0.f; }
        }
        #pragma unroll
        for (int j = 0; j < 4; j++) {
            int l = lb + j;
            float xc = bx4[j];
            float ucur = siluf(fmaf(w0, xm3, fmaf(w1, xm2, fmaf(w2, xm1, w3 * xc))));
            xm3 = xm2; xm2 = xm1; xm1 = xc;
            float dtc = bdt4[j], cc = bc4[j], zc = bz4[j];
            float de = (l == 0) ? dtc : dd;
            float ue = (l == 0) ? ucur : uu;
            float At = __expf(de * av);
            float Bt = smallA ? de : (At - 1.0f) * invA;
            h = fmaf(At, h, Bt * ue);
            float cur = cc * h;

            float x1 = __shfl_xor_sync(0xffffffffu, pend, 1);
            float y1 = __shfl_xor_sync(0xffffffffu, mid, 4);
            pend += x1; mid += y1;
            float x2 = __shfl_xor_sync(0xffffffffu, pend, 2);
            float y2 = __shfl_xor_sync(0xffffffffu, mid, 8);
            pend += x2; mid += y2;
            if (n == 0 && l >= 2) {
                float v = (mid + u_h2 * D) * siluf(z_h2);
                yp[(size_t)(l - 2) * EDIM] = __float2half_rn(v);
            }
            mid = pend; pend = cur;
            u_h2 = u_h1; u_h1 = ucur;
            z_h2 = z_h1; z_h1 = zc;
            dd = dtc; uu = ucur;
        }
        #pragma unroll
        for (int j = 0; j < 4; j++) { bx4[j]=nx4[j]; bdt4[j]=ndt4[j]; bc4[j]=nc4[j]; bz4[j]=nz4[j]; }
    }
    // drain step 1
    {
        float x1 = __shfl_xor_sync(0xffffffffu, pend, 1);
        float y1 = __shfl_xor_sync(0xffffffffu, mid, 4);
        pend += x1; mid += y1;
        float x2 = __shfl_xor_sync(0xffffffffu, pend, 2);
        float y2 = __shfl_xor_sync(0xffffffffu, mid, 8);
        pend += x2; mid += y2;
        if (n == 0) {
            float v = (mid + u_h2 * D) * siluf(z_h2);
            yp[(size_t)(LL - 2) * EDIM] = __float2half_rn(v);
        }
        mid = pend;
    }
    // drain step 2
    {
        float y1 = __shfl_xor_sync(0xffffffffu, mid, 4);
        mid += y1;
        float y2 = __shfl_xor_sync(0xffffffffu, mid, 8);
        mid += y2;
        if (n == 0) {
            float v = (mid + u_h1 * D) * siluf(z_h1);
            yp[(size_t)(LL - 1) * EDIM] = __float2half_rn(v);
        }
    }
}

// ================= fp16 2-term mma GEMM: 64x64 tile, 4 warps, 3-stage ========
// OUT: 0 = store f32, 1 = accumulate f32, 2 = store fp16, 3 = store f32+fp16.
#define GSTAGE 12288
#define GSMEM  (3*GSTAGE)

__device__ __forceinline__ void g_load_stage(
    uint32_t st, const fp16* __restrict__ A,
    const fp16* __restrict__ Bh, const fp16* __restrict__ Bl,
    int lda, int ldb, int koff, int tid)
{
    int r = tid >> 1;                // 0..63
    int gb = (tid & 1) * 2;
    size_t roA = (size_t)r * lda + koff;
    size_t roB = (size_t)r * ldb + koff;
    #pragma unroll
    for (int gi = 0; gi < 2; gi++) {
        int g = gb + gi;
        uint32_t so = (uint32_t)(r * 64 + ((g ^ ((r >> 1) & 3)) << 4));
        CP_ASYNC16(st + so,          A  + roA + g * 8);
        CP_ASYNC16(st + 4096 + so,   Bh + roB + g * 8);
        CP_ASYNC16(st + 8192 + so,   Bl + roB + g * 8);
    }
}

template<int ACT, bool BIAS, int OUT>
__global__ void __launch_bounds__(128, 6) gemm_f16(
    const fp16* __restrict__ A,
    const fp16* __restrict__ Bh, const fp16* __restrict__ Bl,
    int lda, int ldb, int K, const float* __restrict__ bias,
    float* __restrict__ C, fp16* __restrict__ Cf,
    int ldc, int nmax)
{
    extern __shared__ __align__(16) unsigned char smem_raw[];
    uint32_t sb = smem_to_u32(smem_raw);

    int tid = threadIdx.x;
    int wid = tid >> 5, lid = tid & 31;
    int wm = wid & 1, wn = wid >> 1;     // 2(m) x 2(n)

    const fp16* A0  = A  + (size_t)(blockIdx.x * 64) * lda;
    const fp16* Bh0 = Bh + (size_t)(blockIdx.y * 64) * ldb;
    const fp16* Bl0 = Bl + (size_t)(blockIdx.y * 64) * ldb;

    float acc[2][4][4];
    #pragma unroll
    for (int i = 0; i < 2; i++)
        #pragma unroll
        for (int j = 0; j < 4; j++)
            #pragma unroll
            for (int q = 0; q < 4; q++) acc[i][j][q] = 0.f;

    int NC = K / 32;
    g_load_stage(sb, A0, Bh0, Bl0, lda, ldb, 0, tid);
    CP_COMMIT();
    g_load_stage(sb + GSTAGE, A0, Bh0, Bl0, lda, ldb, 32, tid);
    CP_COMMIT();

    for (int c = 0; c < NC; c++) {
        if (c + 1 < NC) { CP_WAIT(1); } else { CP_WAIT(0); }
        __syncthreads();
        if (c + 2 < NC) {
            g_load_stage(sb + ((c + 2) % 3) * GSTAGE, A0, Bh0, Bl0, lda, ldb, (c + 2) * 32, tid);
            CP_COMMIT();
        }

        uint32_t st = sb + (c % 3) * GSTAGE;
        uint32_t sA = st, sBh = st + 4096, sBl = st + 8192;

        #pragma unroll
        for (int ks = 0; ks < 2; ks++) {
            int kch = 2 * ks + (lid >> 4);
            uint32_t bh[2][4], bl_[2][4];
            #pragma unroll
            for (int j2 = 0; j2 < 2; j2++) {
                int mrow = wn * 32 + j2 * 16 + ((lid >> 3) & 1) * 8 + (lid & 7);
                uint32_t off = (uint32_t)(mrow * 64)
                             + (((uint32_t)kch ^ (((uint32_t)mrow >> 1) & 3u)) << 4);
                ldsm_x4(bh[j2][0], bh[j2][1], bh[j2][2], bh[j2][3], sBh + off);
                ldsm_x4(bl_[j2][0], bl_[j2][1], bl_[j2][2], bl_[j2][3], sBl + off);
            }
            #pragma unroll
            for (int i = 0; i < 2; i++) {
                int arow = wm * 32 + i * 16 + (lid & 15);
                uint32_t off = (uint32_t)(arow * 64)
                             + (((uint32_t)kch ^ (((uint32_t)arow >> 1) & 3u)) << 4);
                uint32_t ah[4];
                ldsm_x4(ah[0], ah[1], ah[2], ah[3], sA + off);
                #pragma unroll
                for (int j = 0; j < 4; j++) {
                    int j2 = j >> 1, js = j & 1;
                    mma16816h(acc[i][j], ah, bh[j2][js], bh[j2][2 + js]);
                    mma16816h(acc[i][j], ah, bl_[j2][js], bl_[j2][2 + js]);
                }
            }
        }
    }

    int lr = lid >> 2;
    int lc = (lid & 3) * 2;
    #pragma unroll
    for (int i = 0; i < 2; i++) {
        int row = blockIdx.x * 64 + wm * 32 + i * 16 + lr;
        #pragma unroll
        for (int j = 0; j < 4; j++) {
            int col0 = blockIdx.y * 64 + wn * 32 + j * 8 + lc;
            if (col0 < nmax) {
                #pragma unroll
                for (int half = 0; half < 2; half++) {
                    int rr = row + half * 8;
                    float v0 = acc[i][j][half * 2 + 0];
                    float v1 = acc[i][j][half * 2 + 1];
                    if (BIAS) { v0 += bias[col0]; v1 += bias[col0 + 1]; }
                    if (ACT == 1) { v0 = softplusf(v0); v1 = softplusf(v1); }
                    if (ACT == 2) { v0 = geluf(v0); v1 = geluf(v1); }
                    if (OUT == 2) {
                        __half2* pf = (__half2*)(Cf + (size_t)rr * ldc + col0);
                        *pf = __floats2half2_rn(v0, v1);
                    } else if (OUT == 3) {
                        *(float2*)(C + (size_t)rr * ldc + col0) = make_float2(v0, v1);
                        __half2* pf = (__half2*)(Cf + (size_t)rr * ldc + col0);
                        *pf = __floats2half2_rn(v0, v1);
                    } else {
                        float* cp = C + (size_t)rr * ldc + col0;
                        if (OUT == 1) {
                            float2 old = *(const float2*)cp;
                            v0 += old.x; v1 += old.y;
                        }
                        *(float2*)cp = make_float2(v0, v1);
                    }
                }
            }
        }
    }
}

// ================= fp16 2-term head GEMM: 128x128, 8 warps, 3-stage ==========
#define HSTAGE 24576
#define HSMEM  (3*HSTAGE)

__device__ __forceinline__ void h_load_stage(
    uint32_t st, const fp16* __restrict__ A,
    const fp16* __restrict__ Bh, const fp16* __restrict__ Bl,
    int K, int koff, int tid)
{
    int r = tid >> 1;
    int gb = (tid & 1) * 2;
    size_t ro = (size_t)r * K + koff;
    #pragma unroll
    for (int gi = 0; gi < 2; gi++) {
        int g = gb + gi;
        uint32_t so = (uint32_t)(r * 64 + ((g ^ ((r >> 1) & 3)) << 4));
        CP_ASYNC16(st + so,          A  + ro + g * 8);
        CP_ASYNC16(st + 8192 + so,   Bh + ro + g * 8);
        CP_ASYNC16(st + 16384 + so,  Bl + ro + g * 8);
    }
}

__global__ void __launch_bounds__(256, 2) gemm_hd(
    const fp16* __restrict__ A,
    const fp16* __restrict__ Bh, const fp16* __restrict__ Bl,
    int K, const float* __restrict__ bias,
    float* __restrict__ C, int ldc)
{
    extern __shared__ __align__(16) unsigned char smem_raw[];
    uint32_t sb = smem_to_u32(smem_raw);

    int tid = threadIdx.x;
    int wid = tid >> 5, lid = tid & 31;
    int wm = wid & 1, wn = wid >> 1;

    const fp16* A0  = A  + (size_t)(blockIdx.x * 128) * K;
    const fp16* Bh0 = Bh + (size_t)(blockIdx.y * 128) * K;
    const fp16* Bl0 = Bl + (size_t)(blockIdx.y * 128) * K;

    float acc[4][4][4];
    #pragma unroll
    for (int i = 0; i < 4; i++)
        #pragma unroll
        for (int j = 0; j < 4; j++)
            #pragma unroll
            for (int q = 0; q < 4; q++) acc[i][j][q] = 0.f;

    int NC = K / 32;
    h_load_stage(sb, A0, Bh0, Bl0, K, 0, tid);
    CP_COMMIT();
    h_load_stage(sb + HSTAGE, A0, Bh0, Bl0, K, 32, tid);
    CP_COMMIT();

    for (int c = 0; c < NC; c++) {
        if (c + 1 < NC) { CP_WAIT(1); } else { CP_WAIT(0); }
        __syncthreads();
        if (c + 2 < NC) {
            h_load_stage(sb + ((c + 2) % 3) * HSTAGE, A0, Bh0, Bl0, K, (c + 2) * 32, tid);
            CP_COMMIT();
        }

        uint32_t st = sb + (c % 3) * HSTAGE;
        uint32_t sA = st, sBh = st + 8192, sBl = st + 16384;

        #pragma unroll
        for (int ks = 0; ks < 2; ks++) {
            int kch = 2 * ks + (lid >> 4);
            uint32_t bh[2][4], bl_[2][4];
            #pragma unroll
            for (int j2 = 0; j2 < 2; j2++) {
                int mrow = wn * 32 + j2 * 16 + ((lid >> 3) & 1) * 8 + (lid & 7);
                uint32_t off = (uint32_t)(mrow * 64)
                             + (((uint32_t)kch ^ (((uint32_t)mrow >> 1) & 3u)) << 4);
                ldsm_x4(bh[j2][0], bh[j2][1], bh[j2][2], bh[j2][3], sBh + off);
                ldsm_x4(bl_[j2][0], bl_[j2][1], bl_[j2][2], bl_[j2][3], sBl + off);
            }
            #pragma unroll
            for (int i = 0; i < 4; i++) {
                int arow = wm * 64 + i * 16 + (lid & 15);
                uint32_t off = (uint32_t)(arow * 64)
                             + (((uint32_t)kch ^ (((uint32_t)arow >> 1) & 3u)) << 4);
                uint32_t ah[4];
                ldsm_x4(ah[0], ah[1], ah[2], ah[3], sA + off);
                #pragma unroll
                for (int j = 0; j < 4; j++) {
                    int j2 = j >> 1, js = j & 1;
                    mma16816h(acc[i][j], ah, bh[j2][js], bh[j2][2 + js]);
                    mma16816h(acc[i][j], ah, bl_[j2][js], bl_[j2][2 + js]);
                }
            }
        }
    }

    int lr = lid >> 2;
    int lc = (lid & 3) * 2;
    #pragma unroll
    for (int i = 0; i < 4; i++) {
        int row = blockIdx.x * 128 + wm * 64 + i * 16 + lr;
        #pragma unroll
        for (int j = 0; j < 4; j++) {
            int col0 = blockIdx.y * 128 + wn * 32 + j * 8 + lc;
            #pragma unroll
            for (int half = 0; half < 2; half++) {
                int rr = row + half * 8;
                float v0 = acc[i][j][half * 2 + 0] + bias[col0];
                float v1 = acc[i][j][half * 2 + 1] + bias[col0 + 1];
                *(float2*)(C + (size_t)rr * ldc + col0) = make_float2(v0, v1);
            }
        }
    }
}

// ---------------- launch ----------------
extern "C" void kernel_launch(void* const* d_in, const int* in_sizes, int n_in,
                              void* d_out, int out_size) {
    const int*   tokens    = (const int*)  d_in[0];
    const int*   timesteps = (const int*)  d_in[1];
    const float* tok_emb   = (const float*)d_in[2];
    const float* time_w1   = (const float*)d_in[3];
    const float* time_b1   = (const float*)d_in[4];
    const float* time_w2   = (const float*)d_in[5];
    const float* time_b2   = (const float*)d_in[6];
    const float* ln1_g     = (const float*)d_in[7];
    const float* ln1_b     = (const float*)d_in[8];
    const float* z_w       = (const float*)d_in[9];
    const float* p_w       = (const float*)d_in[10];
    const float* conv_w    = (const float*)d_in[11];
    const float* dtp_w     = (const float*)d_in[12];
    const float* dtp_b     = (const float*)d_in[13];
    const float* A_log     = (const float*)d_in[14];
    const float* D_param   = (const float*)d_in[15];
    const float* out_w     = (const float*)d_in[16];
    const float* ln2_g     = (const float*)d_in[17];
    const float* ln2_b     = (const float*)d_in[18];
    const float* mlp_w1    = (const float*)d_in[19];
    const float* mlp_b1    = (const float*)d_in[20];
    const float* mlp_w2    = (const float*)d_in[21];
    const float* mlp_b2    = (const float*)d_in[22];
    const float* lnout_g   = (const float*)d_in[23];
    const float* lnout_b   = (const float*)d_in[24];
    const float* head_w    = (const float*)d_in[25];
    const float* head_b    = (const float*)d_in[26];

    #define GETP(sym, var, type) void* _p_##var; cudaGetSymbolAddress(&_p_##var, sym); type* var = (type*)_p_##var
    GETP(g_x, bx, float);       GETP(g_xn, bxn, float);
    GETP(g_zp, bzp, float);     GETP(g_dt, bdt, float);
    GETP(g_thid, bthid, float); GETP(g_temb, btemb, float);
    GETP(g_xnf, bxnf, fp16);    GETP(g_zpf, bzpf, fp16);
    GETP(g_yf, byf, fp16);      GETP(g_hidf, bhidf, fp16);
    GETP(g_wzp_h, wzph, fp16);  GETP(g_wzp_l, wzpl, fp16);
    GETP(g_wout_h, wouth, fp16);GETP(g_wout_l, woutl, fp16);
    GETP(g_wm1_h, wm1h, fp16);  GETP(g_wm1_l, wm1l, fp16);
    GETP(g_wm2_h, wm2h, fp16);  GETP(g_wm2_l, wm2l, fp16);
    GETP(g_whd_h, whdh, fp16);  GETP(g_whd_l, whdl, fp16);
    GETP(g_wdt_h, wdth, fp16);  GETP(g_wdt_l, wdtl, fp16);
    #undef GETP

    cudaFuncSetAttribute(gemm_f16<0,false,3>, cudaFuncAttributeMaxDynamicSharedMemorySize, GSMEM);
    cudaFuncSetAttribute(gemm_f16<1,true, 0>, cudaFuncAttributeMaxDynamicSharedMemorySize, GSMEM);
    cudaFuncSetAttribute(gemm_f16<0,false,1>, cudaFuncAttributeMaxDynamicSharedMemorySize, GSMEM);
    cudaFuncSetAttribute(gemm_f16<2,true, 2>, cudaFuncAttributeMaxDynamicSharedMemorySize, GSMEM);
    cudaFuncSetAttribute(gemm_f16<0,true, 1>, cudaFuncAttributeMaxDynamicSharedMemorySize, GSMEM);
    cudaFuncSetAttribute(gemm_hd, cudaFuncAttributeMaxDynamicSharedMemorySize, HSMEM);

    // 1: fused weight conversion + time_mlp1
    cvt_tm1_kernel<<<NWB + TM1B, 256>>>(
        z_w, p_w, out_w, mlp_w1, mlp_w2, head_w, dtp_w,
        wzph, wzpl, wouth, woutl, wm1h, wm1l, wm2h, wm2l, whdh, whdl, wdth, wdtl,
        timesteps, time_w1, time_b1, bthid);
    // 2: time_mlp2
    time_mlp2<<<(NB*EDIM*32 + 255)/256, 256>>>(time_w2, time_b2, bthid, btemb);
    // 3: embed + layer-0 LN1
    embed_ln1_kernel<<<BL, 256>>>(tokens, tok_emb, btemb, ln1_g, ln1_b,
                                  bx, bxn, bxnf);

    for (int i = 0; i < NDEPTH; i++) {
        const fp16* wzph_i = wzph + (size_t)i * ZPNP * EDIM;
        const fp16* wzpl_i = wzpl + (size_t)i * ZPNP * EDIM;
        const fp16* wouth_i = wouth + (size_t)i * EDIM * EDIM;
        const fp16* woutl_i = woutl + (size_t)i * EDIM * EDIM;
        const fp16* wm1h_i = wm1h + (size_t)i * HD * EDIM;
        const fp16* wm1l_i = wm1l + (size_t)i * HD * EDIM;
        const fp16* wm2h_i = wm2h + (size_t)i * EDIM * HD;
        const fp16* wm2l_i = wm2l + (size_t)i * EDIM * HD;
        const fp16* wdth_i = wdth + (size_t)i * EDIM * KDT;
        const fp16* wdtl_i = wdtl + (size_t)i * EDIM * KDT;
        const float* cwi  = conv_w + (size_t)i * EDIM * KC;
        const float* dtbi = dtp_b + (size_t)i * EDIM;
        const float* ali  = A_log + (size_t)i * EDIM * NS;
        const float* dpi  = D_param + (size_t)i * EDIM;
        const float* b1i  = mlp_b1 + (size_t)i * HD;
        const float* b2i  = mlp_b2 + (size_t)i * EDIM;

        if (i > 0)
            ln_kernel<<<BL, 256>>>(bx, bxn, bxnf, ln1_g + i*EDIM, ln1_b + i*EDIM);
        // 4 (first iter): zp GEMM (writes f32 + fp16) — in ncu capture window
        gemm_f16<0,false,3><<<dim3(BL/64, ZPNP/64), 128, GSMEM>>>(
            bxnf, wzph_i, wzpl_i, EDIM, EDIM, EDIM, nullptr, bzp, bzpf, ZPNP, ZPNP);
        // dt = softplus(zp[:, 768:832] @ wdt^T + b)  (tensor path, K=64 padded)
        gemm_f16<1,true,0><<<dim3(BL/64, EDIM/64), 128, GSMEM>>>(
            bzpf + EDIM, wdth_i, wdtl_i, ZPNP, KDT, KDT, dtbi, bdt, nullptr, EDIM, EDIM);
        // scan (fused conv+silu, batch-4 prefetch, gating)
        scan_kernel<<<(NB*EDIM*NS + 127)/128, 128>>>(ali, dpi, bdt, bxn, cwi, bzp, byf);
        gemm_f16<0,false,1><<<dim3(BL/64, EDIM/64), 128, GSMEM>>>(
            byf, wouth_i, woutl_i, EDIM, EDIM, EDIM, nullptr, bx, nullptr, EDIM, EDIM);
        ln_kernel<<<BL, 256>>>(bx, bxn, bxnf, ln2_g + i*EDIM, ln2_b + i*EDIM);
        gemm_f16<2,true,2><<<dim3(BL/64, HD/64), 128, GSMEM>>>(
            bxnf, wm1h_i, wm1l_i, EDIM, EDIM, EDIM, b1i, nullptr, bhidf, HD, HD);
        gemm_f16<0,true,1><<<dim3(BL/64, EDIM/64), 128, GSMEM>>>(
            bhidf, wm2h_i, wm2l_i, HD, HD, HD, b2i, bx, nullptr, EDIM, EDIM);
    }

    ln_kernel<<<BL, 256>>>(bx, bxn, bxnf, lnout_g, lnout_b);
    gemm_hd<<<dim3(BL/128, VOC/128), 256, HSMEM>>>(
        bxnf, whdh, whdl, EDIM, head_b, (float*)d_out, VOC);
}